// round 14
// baseline (speedup 1.0000x reference)
#include <cuda_runtime.h>
#include <cuda_fp16.h>
#include <cstdint>
#include <math.h>

#define BSZ 8
#define SEQ 1024
#define DIM 768
#define NH  12
#define DKH 64
#define NL  3
#define MTOT (BSZ*SEQ)
#define D2   (DIM*DIM)

__device__ __half g_qin [MTOT*DIM];
__device__ __half g_kin [MTOT*DIM];
__device__ __half g_vin [MTOT*DIM];
__device__ __half g_qh  [MTOT*DIM];
__device__ __half g_kh  [MTOT*DIM];
__device__ __half g_vt  [MTOT*DIM];   // V transposed per (b): [(b*768+d)][SEQ]
__device__ __half g_ctx [MTOT*DIM];
__device__ __half g_wq  [NL*D2];
__device__ __half g_wk  [NL*D2];
__device__ __half g_wv  [NL*D2];
__device__ __half g_wo  [NL*D2];
__device__ __half g_woT [2*D2];       // Wo^T of layers 0,1
__device__ __half g_wkv [4*D2];       // folded Wk1Wo0, Wv1Wo0, Wk2Wo1, Wv2Wo1
__device__ float  g_bkv [4*DIM];
__device__ float  g_zero[DIM];        // zero-initialized

__device__ __forceinline__ uint32_t smem_u32(const void* p) {
    uint32_t a;
    asm("{ .reg .u64 t; cvta.to.shared.u64 t, %1; cvt.u32.u64 %0, t; }"
        : "=r"(a) : "l"(p));
    return a;
}
// pack two fp32 -> fp16x2 (lo = first arg in memory order)
__device__ __forceinline__ uint32_t pack_h(float lo, float hi) {
    uint32_t r;
    asm("cvt.rn.f16x2.f32 %0, %1, %2;" : "=r"(r) : "f"(hi), "f"(lo));
    return r;
}
__device__ __forceinline__ void mma16(float* d, const uint32_t* a, const uint32_t* b) {
    asm volatile(
        "mma.sync.aligned.m16n8k16.row.col.f32.f16.f16.f32 "
        "{%0,%1,%2,%3}, {%4,%5,%6,%7}, {%8,%9}, {%0,%1,%2,%3};"
        : "+f"(d[0]), "+f"(d[1]), "+f"(d[2]), "+f"(d[3])
        : "r"(a[0]), "r"(a[1]), "r"(a[2]), "r"(a[3]), "r"(b[0]), "r"(b[1]));
}
__device__ __forceinline__ void ldsm4(uint32_t* r, uint32_t addr) {
    asm volatile("ldmatrix.sync.aligned.m8n8.x4.shared.b16 {%0,%1,%2,%3}, [%4];"
        : "=r"(r[0]), "=r"(r[1]), "=r"(r[2]), "=r"(r[3]) : "r"(addr));
}
// paired exp2 in fp16 (1 MUFU op for 2 scores), returns fp32 pair
__device__ __forceinline__ float2 exp2_pair(float s0, float s1) {
    uint32_t h;
    asm("cvt.rn.f16x2.f32 %0, %1, %2;" : "=r"(h) : "f"(s1), "f"(s0));
    asm("ex2.approx.f16x2 %0, %0;" : "+r"(h));
    __half2 e = *reinterpret_cast<__half2*>(&h);
    return __half22float2(e);
}
#define CP_ASYNC16(s, g) \
    asm volatile("cp.async.cg.shared.global [%0], [%1], 16;" \
                 :: "r"(s), "l"(g) : "memory")
#define CP_COMMIT() asm volatile("cp.async.commit_group;" ::: "memory")
template<int N> __device__ __forceinline__ void cp_wait() {
    asm volatile("cp.async.wait_group %0;" :: "n"(N) : "memory");
}

// ---------------- converters / prep ----------------
__global__ void f2h_acts_kernel(
    const float4* __restrict__ a0, const float4* __restrict__ a1,
    const float4* __restrict__ a2,
    uint2* __restrict__ o0, uint2* __restrict__ o1, uint2* __restrict__ o2, int n4)
{
    int i = blockIdx.x * blockDim.x + threadIdx.x;
    if (i >= n4) return;
    const float4* in = blockIdx.y == 0 ? a0 : blockIdx.y == 1 ? a1 : a2;
    uint2* out       = blockIdx.y == 0 ? o0 : blockIdx.y == 1 ? o1 : o2;
    float4 f = in[i];
    out[i] = make_uint2(pack_h(f.x, f.y), pack_h(f.z, f.w));
}
__global__ void f2h_w_kernel(
    const float4* __restrict__ a0, const float4* __restrict__ a1,
    const float4* __restrict__ a2, const float4* __restrict__ a3,
    uint2* __restrict__ o0, uint2* __restrict__ o1,
    uint2* __restrict__ o2, uint2* __restrict__ o3, int n4)
{
    int i = blockIdx.x * blockDim.x + threadIdx.x;
    if (i >= n4) return;
    const float4* in = blockIdx.y == 0 ? a0 : blockIdx.y == 1 ? a1
                     : blockIdx.y == 2 ? a2 : a3;
    uint2* out       = blockIdx.y == 0 ? o0 : blockIdx.y == 1 ? o1
                     : blockIdx.y == 2 ? o2 : o3;
    float4 f = in[i];
    out[i] = make_uint2(pack_h(f.x, f.y), pack_h(f.z, f.w));
}
__global__ void transpose_w_kernel(const __half* __restrict__ src,
                                   __half* __restrict__ dst)
{
    __shared__ __half tile[32][33];
    const int l = blockIdx.z;
    const __half* s = src + (size_t)l * D2;
    __half* d = dst + (size_t)l * D2;
    const int x = blockIdx.x * 32 + threadIdx.x;
    const int y0 = blockIdx.y * 32;
    #pragma unroll
    for (int i = threadIdx.y; i < 32; i += 8)
        tile[i][threadIdx.x] = s[(size_t)(y0 + i) * DIM + x];
    __syncthreads();
    const int x2 = blockIdx.y * 32 + threadIdx.x;
    const int y2 = blockIdx.x * 32;
    #pragma unroll
    for (int i = threadIdx.y; i < 32; i += 8)
        d[(size_t)(y2 + i) * DIM + x2] = tile[threadIdx.x][i];
}
__global__ void biasfold_kernel(
    const float* __restrict__ Wk, const float* __restrict__ Wv,
    const float* __restrict__ bk, const float* __restrict__ bv,
    const float* __restrict__ bo, float* __restrict__ bkv)
{
    const int z = blockIdx.y;
    const int n = blockIdx.x * 128 + threadIdx.x;
    const int li = (z < 2) ? 1 : 2;
    const float* W  = ((z & 1) == 0 ? Wk : Wv) + (size_t)li * D2 + (size_t)n * DIM;
    const float* bs = ((z & 1) == 0 ? bk : bv) + li * DIM;
    const float* bsrc = bo + (li - 1) * DIM;
    float acc = 0.f;
    #pragma unroll 8
    for (int j = 0; j < DIM; j++) acc += W[j] * bsrc[j];
    bkv[z * DIM + n] = acc + bs[n];
}

// ---------------- GEMM core (fp16, ldmatrix, 3-stage) ----------------
#define GPADW 20
#define GSLOTW (128*GPADW)
#define GSTG 3
#define GEMM_SMEM ((128 + GSTG*2*GSLOTW) * 4)   // 61952 B

struct GemmAcc { float a[2][8][4]; };

__device__ __forceinline__ void gemm_mainloop(
    const __half* __restrict__ X, const __half* __restrict__ W,
    const float* __restrict__ bias, float* sBias, uint32_t* sT,
    int m0, int n0, int tid, GemmAcc& A)
{
    const uint32_t tAddr = smem_u32(sT);
    const int lane = tid & 31, wid = tid >> 5;
    const int wm = wid & 3, wn = wid >> 2;
    const int j  = lane >> 3, r7 = lane & 7;
    const int aRow = (j & 1) * 8 + r7, aCol = (j >> 1) * 4;
    const int bRow = (j >> 1) * 8 + r7, bCol = (j & 1) * 4;

    if (tid < 128) sBias[tid] = bias[n0 + tid];

    #pragma unroll
    for (int mt = 0; mt < 2; mt++)
        #pragma unroll
        for (int nt = 0; nt < 8; nt++)
            #pragma unroll
            for (int i = 0; i < 4; i++) A.a[mt][nt][i] = 0.f;

    auto load_chunk = [&](int c) {
        const uint32_t base = tAddr + (uint32_t)(c % GSTG) * (2 * GSLOTW * 4);
        const __half* gA = X + (size_t)m0 * DIM + c * 32;
        const __half* gB = W + (size_t)n0 * DIM + c * 32;
        #pragma unroll
        for (int i = 0; i < 2; i++) {
            int idx = tid + i * 256;
            int row = idx >> 2, f = idx & 3;
            uint32_t d = base + (uint32_t)(row * GPADW + f * 4) * 4;
            const size_t go = (size_t)row * DIM + f * 8;
            CP_ASYNC16(d, gA + go);
            CP_ASYNC16(d + GSLOTW * 4, gB + go);
        }
        CP_COMMIT();
    };

    load_chunk(0);
    load_chunk(1);
    for (int c = 0; c < 24; c++) {
        if (c < 23) cp_wait<1>(); else cp_wait<0>();
        __syncthreads();
        if (c + 2 < 24) load_chunk(c + 2);

        const uint32_t aB = tAddr + (uint32_t)(c % GSTG) * (2 * GSLOTW * 4);
        const uint32_t bB = aB + GSLOTW * 4;

        #pragma unroll
        for (int ks = 0; ks < 2; ks++) {
            uint32_t afr[2][4];
            #pragma unroll
            for (int mt = 0; mt < 2; mt++)
                ldsm4(afr[mt], aB + (uint32_t)((wm * 32 + mt * 16 + aRow) * GPADW
                                               + ks * 8 + aCol) * 4);
            uint32_t bfr[8][2];
            #pragma unroll
            for (int p = 0; p < 4; p++) {
                uint32_t rr[4];
                ldsm4(rr, bB + (uint32_t)((wn * 64 + p * 16 + bRow) * GPADW
                                          + ks * 8 + bCol) * 4);
                bfr[2*p][0]   = rr[0]; bfr[2*p][1]   = rr[1];
                bfr[2*p+1][0] = rr[2]; bfr[2*p+1][1] = rr[3];
            }
            #pragma unroll
            for (int nt = 0; nt < 8; nt++) {
                mma16(A.a[0][nt], afr[0], bfr[nt]);
                mma16(A.a[1][nt], afr[1], bfr[nt]);
            }
        }
    }
}

__global__ __launch_bounds__(256, 2) void gemm_qkv_kernel(
    const __half* __restrict__ xq, const __half* __restrict__ xk,
    const __half* __restrict__ xv,
    const __half* __restrict__ wq, const __half* __restrict__ wk,
    const __half* __restrict__ wv,
    const float* __restrict__ bq, const float* __restrict__ bk,
    const float* __restrict__ bv,
    __half* __restrict__ oq, __half* __restrict__ ok,
    __half* __restrict__ ovt, float qscale)
{
    extern __shared__ __align__(128) float smf[];
    float* sBias = smf;
    uint32_t* sT = (uint32_t*)(smf + 128);

    const int tid = threadIdx.x;
    const int slice = blockIdx.x / 6;
    const int n0 = (blockIdx.x % 6) * 128;
    const int m0 = blockIdx.y * 128;

    const __half* X = slice == 0 ? xq : slice == 1 ? xk : xv;
    const __half* W = slice == 0 ? wq : slice == 1 ? wk : wv;
    const float*  B = slice == 0 ? bq : slice == 1 ? bk : bv;

    GemmAcc A;
    gemm_mainloop(X, W, B, sBias, sT, m0, n0, tid, A);

    const int lane = tid & 31, wid = tid >> 5;
    const int g = lane >> 2, t = lane & 3;
    const int wm = wid & 3, wn = wid >> 2;
    const float scale = slice == 0 ? qscale : 1.0f;

    #pragma unroll
    for (int mt = 0; mt < 2; mt++) {
        const int m = m0 + wm * 32 + mt * 16 + g;
        #pragma unroll
        for (int nt = 0; nt < 8; nt++) {
            const int nl = wn * 64 + nt * 8 + 2 * t;
            float v0x = (A.a[mt][nt][0] + sBias[nl])     * scale;
            float v0y = (A.a[mt][nt][1] + sBias[nl + 1]) * scale;
            float v1x = (A.a[mt][nt][2] + sBias[nl])     * scale;
            float v1y = (A.a[mt][nt][3] + sBias[nl + 1]) * scale;
            if (slice < 2) {
                __half* ob = slice == 0 ? oq : ok;
                *(uint32_t*)(ob + (size_t)m * DIM + n0 + nl)       = pack_h(v0x, v0y);
                *(uint32_t*)(ob + (size_t)(m + 8) * DIM + n0 + nl) = pack_h(v1x, v1y);
            } else {
                const int n = n0 + nl;
                const size_t rb = (size_t)((m >> 10) * 768);
                const int s = m & (SEQ - 1);
                ovt[(rb + n)     * SEQ + s]     = __float2half(v0x);
                ovt[(rb + n + 1) * SEQ + s]     = __float2half(v0y);
                ovt[(rb + n)     * SEQ + s + 8] = __float2half(v1x);
                ovt[(rb + n + 1) * SEQ + s + 8] = __float2half(v1y);
            }
        }
    }
}

__global__ __launch_bounds__(256, 2) void fold_gemm_kernel(
    const __half* __restrict__ wk, const __half* __restrict__ wv,
    const __half* __restrict__ woT, const float* __restrict__ zero,
    __half* __restrict__ wkv)
{
    extern __shared__ __align__(128) float smf[];
    float* sBias = smf;
    uint32_t* sT = (uint32_t*)(smf + 128);

    const int tid = threadIdx.x;
    const int n0 = blockIdx.x * 128;
    const int m0 = blockIdx.y * 128;
    const int z  = blockIdx.z;
    const int li = (z < 2) ? 1 : 2;

    const __half* A = ((z & 1) == 0 ? wk : wv) + (size_t)li * D2;
    const __half* W = woT + (size_t)(li - 1) * D2;
    __half* O = wkv + (size_t)z * D2;

    GemmAcc Ac;
    gemm_mainloop(A, W, zero, sBias, sT, m0, n0, tid, Ac);

    const int lane = tid & 31, wid = tid >> 5;
    const int g = lane >> 2, t = lane & 3;
    const int wm = wid & 3, wn = wid >> 2;

    #pragma unroll
    for (int mt = 0; mt < 2; mt++) {
        const int m = m0 + wm * 32 + mt * 16 + g;
        #pragma unroll
        for (int nt = 0; nt < 8; nt++) {
            const int nl = wn * 64 + nt * 8 + 2 * t;
            *(uint32_t*)(O + (size_t)m * DIM + n0 + nl) =
                pack_h(Ac.a[mt][nt][0], Ac.a[mt][nt][1]);
            *(uint32_t*)(O + (size_t)(m + 8) * DIM + n0 + nl) =
                pack_h(Ac.a[mt][nt][2], Ac.a[mt][nt][3]);
        }
    }
}

__global__ __launch_bounds__(256, 2) void gemm_ofin_kernel(
    const __half* __restrict__ X, const __half* __restrict__ W,
    const float* __restrict__ bias, const float* __restrict__ add,
    float* __restrict__ out)
{
    extern __shared__ __align__(128) float smf[];
    float* sBias = smf;
    uint32_t* sT = (uint32_t*)(smf + 128);

    const int tid = threadIdx.x;
    const int n0 = blockIdx.x * 128;
    const int m0 = blockIdx.y * 128;

    GemmAcc A;
    gemm_mainloop(X, W, bias, sBias, sT, m0, n0, tid, A);

    const int lane = tid & 31, wid = tid >> 5;
    const int g = lane >> 2, t = lane & 3;
    const int wm = wid & 3, wn = wid >> 2;

    #pragma unroll
    for (int mt = 0; mt < 2; mt++) {
        const int m = m0 + wm * 32 + mt * 16 + g;
        #pragma unroll
        for (int nt = 0; nt < 8; nt++) {
            const int nl = wn * 64 + nt * 8 + 2 * t;
            const size_t o0 = (size_t)m * DIM + n0 + nl;
            const size_t o1 = (size_t)(m + 8) * DIM + n0 + nl;
            float2 a0 = *reinterpret_cast<const float2*>(add + o0);
            float2 a1 = *reinterpret_cast<const float2*>(add + o1);
            *reinterpret_cast<float2*>(out + o0) =
                make_float2(A.a[mt][nt][0] + sBias[nl] + a0.x,
                            A.a[mt][nt][1] + sBias[nl + 1] + a0.y);
            *reinterpret_cast<float2*>(out + o1) =
                make_float2(A.a[mt][nt][2] + sBias[nl] + a1.x,
                            A.a[mt][nt][3] + sBias[nl + 1] + a1.y);
        }
    }
}

// ---------------- fp16 flash attention (pipelined S, register P) ----------------
#define APW 36
#define KV_SLOTW (64*APW*2)
#define ASTG 3
#define QP_OFFW  (ASTG*KV_SLOTW)
#define ATTN_SMEM ((ASTG*KV_SLOTW + 128*APW) * 4)   // 73728 B

__global__ __launch_bounds__(256, 2) void attn_h_kernel(
    const __half* __restrict__ q, const __half* __restrict__ k,
    const __half* __restrict__ vt, const float* __restrict__ dist,
    __half* __restrict__ ctx)
{
    extern __shared__ __align__(128) uint32_t smw[];
    const uint32_t base = smem_u32(smw);
    uint32_t* sQP = smw + QP_OFFW;

    const int tid  = threadIdx.x;
    const int lane = tid & 31, wid = tid >> 5;
    const int g = lane >> 2, t = lane & 3;
    const int j  = lane >> 3, r7 = lane & 7;
    const int bRow = (j >> 1) * 8 + r7, bCol = (j & 1) * 4;

    const int b = blockIdx.z, h = blockIdx.y;
    const int q0 = blockIdx.x * 128;

    const __half* qb = q + (size_t)b * SEQ * DIM + h * DKH;
    const __half* kb = k + (size_t)b * SEQ * DIM + h * DKH;
    const __half* vb = vt + ((size_t)b * 768 + h * DKH) * SEQ;
    const float* db = dist + (size_t)b * SEQ * SEQ;

    // ---- load Q tile 128x64 fp16 ----
    {
        const uint32_t qdst = base + QP_OFFW * 4;
        #pragma unroll
        for (int i = 0; i < 4; i++) {
            int idx = tid + i * 256;
            int row = idx >> 3, f = idx & 7;
            CP_ASYNC16(qdst + (uint32_t)(row * APW + f * 4) * 4,
                       qb + (size_t)(q0 + row) * DIM + f * 8);
        }
        CP_COMMIT();
        cp_wait<0>();
        __syncthreads();
    }

    uint32_t qf[4][4];
    {
        const uint32_t* qp0 = sQP + (wid * 16 + g) * APW;
        const uint32_t* qp1 = qp0 + 8 * APW;
        #pragma unroll
        for (int ks = 0; ks < 4; ks++) {
            qf[ks][0] = qp0[ks * 8 + t];
            qf[ks][1] = qp1[ks * 8 + t];
            qf[ks][2] = qp0[ks * 8 + t + 4];
            qf[ks][3] = qp1[ks * 8 + t + 4];
        }
    }
    __syncthreads();

    float Of[8][4];
    #pragma unroll
    for (int nt = 0; nt < 8; nt++)
        #pragma unroll
        for (int i = 0; i < 4; i++) Of[nt][i] = 0.f;
    float m_run0 = -1e30f, m_run1 = -1e30f, z_run0 = 0.f, z_run1 = 0.f;
    const int qi0 = q0 + wid * 16 + g;
    const int qi1 = qi0 + 8;

    auto load_kv = [&](int kt) {
        const uint32_t dst = base + (uint32_t)(kt % ASTG) * (KV_SLOTW * 4);
        const __half* gk = kb + (size_t)kt * 64 * DIM;
        const __half* gv = vb + kt * 64;
        #pragma unroll
        for (int i = 0; i < 2; i++) {
            int idx = tid + i * 256;
            int row = idx >> 3, f = idx & 7;
            CP_ASYNC16(dst + (uint32_t)(row * APW + f * 4) * 4,
                       gk + (size_t)row * DIM + f * 8);
            CP_ASYNC16(dst + (uint32_t)(64 * APW + row * APW + f * 4) * 4,
                       gv + (size_t)row * SEQ + f * 8);
        }
        CP_COMMIT();
    };

    float Sf[8][4];
    // compute S for the tile in `slot` into Sf (zero + accumulate)
    auto computeS = [&](int slot) {
        const uint32_t ksAddr = base + (uint32_t)slot * (KV_SLOTW * 4);
        #pragma unroll
        for (int nt = 0; nt < 8; nt++)
            #pragma unroll
            for (int i = 0; i < 4; i++) Sf[nt][i] = 0.f;
        #pragma unroll
        for (int ks = 0; ks < 4; ks++) {
            uint32_t kf[8][2];
            #pragma unroll
            for (int p = 0; p < 4; p++) {
                uint32_t rr[4];
                ldsm4(rr, ksAddr + (uint32_t)((p * 16 + bRow) * APW
                                              + ks * 8 + bCol) * 4);
                kf[2*p][0]   = rr[0]; kf[2*p][1]   = rr[1];
                kf[2*p+1][0] = rr[2]; kf[2*p+1][1] = rr[3];
            }
            #pragma unroll
            for (int nt = 0; nt < 8; nt++)
                mma16(Sf[nt], qf[ks], kf[nt]);
        }
    };

    // prologue: kv0, kv1 in flight; S_0 once kv0 arrives
    load_kv(0);
    load_kv(1);
    cp_wait<1>();
    __syncthreads();
    computeS(0);

    for (int kt = 0; kt < 16; kt++) {
        // all kv through kt+1 arrived; all warps done reading tile kt-1
        cp_wait<0>();
        __syncthreads();
        if (kt + 2 < 16) load_kv(kt + 2);

        const uint32_t vsAddr = base + (uint32_t)(kt % ASTG) * (KV_SLOTW * 4)
                              + 64 * APW * 4;
        const int kbase = kt * 64;

        // ---- online softmax on Sf (= S_kt) ----
        float mloc0 = -1e30f, mloc1 = -1e30f;
        #pragma unroll
        for (int nt = 0; nt < 8; nt++) {
            mloc0 = fmaxf(mloc0, fmaxf(Sf[nt][0], Sf[nt][1]));
            mloc1 = fmaxf(mloc1, fmaxf(Sf[nt][2], Sf[nt][3]));
        }
        #pragma unroll
        for (int off = 1; off <= 2; off <<= 1) {
            mloc0 = fmaxf(mloc0, __shfl_xor_sync(0xffffffffu, mloc0, off));
            mloc1 = fmaxf(mloc1, __shfl_xor_sync(0xffffffffu, mloc1, off));
        }
        const float mnew0 = fmaxf(m_run0, mloc0);
        const float mnew1 = fmaxf(m_run1, mloc1);
        const float f0 = exp2f(m_run0 - mnew0);
        const float f1 = exp2f(m_run1 - mnew1);
        z_run0 *= f0; z_run1 *= f1;
        #pragma unroll
        for (int nt = 0; nt < 8; nt++) {
            Of[nt][0] *= f0; Of[nt][1] *= f0;
            Of[nt][2] *= f1; Of[nt][3] *= f1;
        }

        // ---- exp + mask -> P in registers (== PV A-fragments) ----
        float zs0 = 0.f, zs1 = 0.f;
        uint32_t Pr0[8], Pr1[8];
        #pragma unroll
        for (int h2 = 0; h2 < 2; h2++) {
            float2 md0[4], md1[4];
            #pragma unroll
            for (int jj = 0; jj < 4; jj++) {
                const int nt = h2 * 4 + jj;
                const int ki = kbase + nt * 8 + 2 * t;
                md0[jj] = *reinterpret_cast<const float2*>(
                    db + (size_t)qi0 * SEQ + ki);
                md1[jj] = *reinterpret_cast<const float2*>(
                    db + (size_t)qi1 * SEQ + ki);
                if (qi0 == ki)     md0[jj].x += 1.f;
                if (qi0 == ki + 1) md0[jj].y += 1.f;
                if (qi1 == ki)     md1[jj].x += 1.f;
                if (qi1 == ki + 1) md1[jj].y += 1.f;
            }
            #pragma unroll
            for (int jj = 0; jj < 4; jj++) {
                const int nt = h2 * 4 + jj;
                float2 e01 = exp2_pair(Sf[nt][0] - mnew0, Sf[nt][1] - mnew0);
                float2 e23 = exp2_pair(Sf[nt][2] - mnew1, Sf[nt][3] - mnew1);
                zs0 += e01.x + e01.y;
                zs1 += e23.x + e23.y;
                Pr0[nt] = pack_h(e01.x * md0[jj].x, e01.y * md0[jj].y);
                Pr1[nt] = pack_h(e23.x * md1[jj].x, e23.y * md1[jj].y);
            }
        }
        #pragma unroll
        for (int off = 1; off <= 2; off <<= 1) {
            zs0 += __shfl_xor_sync(0xffffffffu, zs0, off);
            zs1 += __shfl_xor_sync(0xffffffffu, zs1, off);
        }
        z_run0 += zs0; z_run1 += zs1;
        m_run0 = mnew0; m_run1 = mnew1;

        // ---- pipeline: S_{kt+1} mma (Sf regs now free) ----
        if (kt + 1 < 16)
            computeS((kt + 1) % ASTG);

        // ---- O += P V (overlaps with next iteration's softmax drain) ----
        #pragma unroll
        for (int ks = 0; ks < 4; ks++) {
            uint32_t af[4] = { Pr0[2*ks], Pr1[2*ks], Pr0[2*ks+1], Pr1[2*ks+1] };
            uint32_t vf[8][2];
            #pragma unroll
            for (int p = 0; p < 4; p++) {
                uint32_t rr[4];
                ldsm4(rr, vsAddr + (uint32_t)((p * 16 + bRow) * APW
                                              + ks * 8 + bCol) * 4);
                vf[2*p][0]   = rr[0]; vf[2*p][1]   = rr[1];
                vf[2*p+1][0] = rr[2]; vf[2*p+1][1] = rr[3];
            }
            #pragma unroll
            for (int nt = 0; nt < 8; nt++)
                mma16(Of[nt], af, vf[nt]);
        }
    }

    const float inv0 = 1.f / z_run0, inv1 = 1.f / z_run1;
    #pragma unroll
    for (int nt = 0; nt < 8; nt++) {
        const int d = h * DKH + nt * 8 + 2 * t;
        *(uint32_t*)(ctx + ((size_t)b * SEQ + qi0) * DIM + d) =
            pack_h(Of[nt][0] * inv0, Of[nt][1] * inv0);
        *(uint32_t*)(ctx + ((size_t)b * SEQ + qi1) * DIM + d) =
            pack_h(Of[nt][2] * inv1, Of[nt][3] * inv1);
    }
}

// ---------------- host ----------------
extern "C" void kernel_launch(void* const* d_in, const int* in_sizes, int n_in,
                              void* d_out, int out_size)
{
    const float* Q    = (const float*)d_in[0];
    const float* Kin  = (const float*)d_in[1];
    const float* Vin  = (const float*)d_in[2];
    const float* dist = (const float*)d_in[3];
    const float* Wq   = (const float*)d_in[4];
    const float* bq   = (const float*)d_in[5];
    const float* Wk   = (const float*)d_in[6];
    const float* bk   = (const float*)d_in[7];
    const float* Wv   = (const float*)d_in[8];
    const float* bv   = (const float*)d_in[9];
    const float* Wo   = (const float*)d_in[10];
    const float* bo   = (const float*)d_in[11];
    float* out = (float*)d_out;

    __half *qin, *kin, *vin, *qh, *kh, *vtb, *ctxb;
    __half *wqh, *wkh, *wvh, *woh, *woT, *wkv;
    float *bkv, *zero;
    cudaGetSymbolAddress((void**)&qin,  g_qin);
    cudaGetSymbolAddress((void**)&kin,  g_kin);
    cudaGetSymbolAddress((void**)&vin,  g_vin);
    cudaGetSymbolAddress((void**)&qh,   g_qh);
    cudaGetSymbolAddress((void**)&kh,   g_kh);
    cudaGetSymbolAddress((void**)&vtb,  g_vt);
    cudaGetSymbolAddress((void**)&ctxb, g_ctx);
    cudaGetSymbolAddress((void**)&wqh,  g_wq);
    cudaGetSymbolAddress((void**)&wkh,  g_wk);
    cudaGetSymbolAddress((void**)&wvh,  g_wv);
    cudaGetSymbolAddress((void**)&woh,  g_wo);
    cudaGetSymbolAddress((void**)&woT,  g_woT);
    cudaGetSymbolAddress((void**)&wkv,  g_wkv);
    cudaGetSymbolAddress((void**)&bkv,  g_bkv);
    cudaGetSymbolAddress((void**)&zero, g_zero);

    cudaFuncSetAttribute(gemm_qkv_kernel,
                         cudaFuncAttributeMaxDynamicSharedMemorySize, GEMM_SMEM);
    cudaFuncSetAttribute(fold_gemm_kernel,
                         cudaFuncAttributeMaxDynamicSharedMemorySize, GEMM_SMEM);
    cudaFuncSetAttribute(gemm_ofin_kernel,
                         cudaFuncAttributeMaxDynamicSharedMemorySize, GEMM_SMEM);
    cudaFuncSetAttribute(attn_h_kernel,
                         cudaFuncAttributeMaxDynamicSharedMemorySize, ATTN_SMEM);

    {
        const int nAct4 = MTOT * DIM / 4;
        const int nW4   = NL * D2 / 4;
        dim3 ga((nAct4 + 255) / 256, 3);
        f2h_acts_kernel<<<ga, 256>>>((const float4*)Q, (const float4*)Kin,
                                     (const float4*)Vin,
                                     (uint2*)qin, (uint2*)kin, (uint2*)vin, nAct4);
        dim3 gw((nW4 + 255) / 256, 4);
        f2h_w_kernel<<<gw, 256>>>((const float4*)Wq, (const float4*)Wk,
                                  (const float4*)Wv, (const float4*)Wo,
                                  (uint2*)wqh, (uint2*)wkh, (uint2*)wvh, (uint2*)woh, nW4);
        dim3 gt(24, 24, 2);
        transpose_w_kernel<<<gt, dim3(32, 8)>>>(woh, woT);
        dim3 gf(6, 6, 4);
        fold_gemm_kernel<<<gf, 256, GEMM_SMEM>>>(wkh, wvh, woT, zero, wkv);
        dim3 gb(6, 4);
        biasfold_kernel<<<gb, 128>>>(Wk, Wv, bk, bv, bo, bkv);
    }

    const float qscale = 0.125f * 1.4426950408889634f;  // log2(e)/sqrt(64)
    dim3 qkvgrid(18, MTOT / 128);
    dim3 ogrid(DIM / 128, MTOT / 128);
    dim3 agrid(SEQ / 128, NH, BSZ);

    // layer 1
    gemm_qkv_kernel<<<qkvgrid, 256, GEMM_SMEM>>>(
        qin, kin, vin, wqh, wkh, wvh, bq, bk, bv, qh, kh, vtb, qscale);
    attn_h_kernel<<<agrid, 256, ATTN_SMEM>>>(qh, kh, vtb, dist, ctxb);
    // layer 2 (folded K/V from ctx)
    gemm_qkv_kernel<<<qkvgrid, 256, GEMM_SMEM>>>(
        qin, ctxb, ctxb, wqh + D2, wkv, wkv + D2,
        bq + DIM, bkv, bkv + DIM, qh, kh, vtb, qscale);
    attn_h_kernel<<<agrid, 256, ATTN_SMEM>>>(qh, kh, vtb, dist, ctxb);
    // layer 3 (folded)
    gemm_qkv_kernel<<<qkvgrid, 256, GEMM_SMEM>>>(
        qin, ctxb, ctxb, wqh + 2 * (size_t)D2, wkv + 2 * (size_t)D2, wkv + 3 * (size_t)D2,
        bq + 2 * DIM, bkv + 2 * DIM, bkv + 3 * DIM, qh, kh, vtb, qscale);
    attn_h_kernel<<<agrid, 256, ATTN_SMEM>>>(qh, kh, vtb, dist, ctxb);
    // final
    gemm_ofin_kernel<<<ogrid, 256, GEMM_SMEM>>>(ctxb, woh + 2 * (size_t)D2,
                                                bo + 2 * DIM, Vin, out);
}

// round 15
// speedup vs baseline: 1.1050x; 1.1050x over previous
#include <cuda_runtime.h>
#include <cuda_fp16.h>
#include <cstdint>
#include <math.h>

#define BSZ 8
#define SEQ 1024
#define DIM 768
#define NH  12
#define DKH 64
#define NL  3
#define MTOT (BSZ*SEQ)
#define D2   (DIM*DIM)

__device__ __half g_qin [MTOT*DIM];
__device__ __half g_kin [MTOT*DIM];
__device__ __half g_vin [MTOT*DIM];
__device__ __half g_qh  [MTOT*DIM];
__device__ __half g_kh  [MTOT*DIM];
__device__ __half g_vt  [MTOT*DIM];   // V transposed per (b): [(b*768+d)][SEQ]
__device__ __half g_ctx [MTOT*DIM];
__device__ __half g_wq  [NL*D2];
__device__ __half g_wk  [NL*D2];
__device__ __half g_wv  [NL*D2];
__device__ __half g_wo  [NL*D2];
__device__ __half g_woT [2*D2];       // Wo^T of layers 0,1
__device__ __half g_wkv [4*D2];       // folded Wk1Wo0, Wv1Wo0, Wk2Wo1, Wv2Wo1
__device__ float  g_bkv [4*DIM];
__device__ float  g_zero[DIM];        // zero-initialized

__device__ __forceinline__ uint32_t smem_u32(const void* p) {
    uint32_t a;
    asm("{ .reg .u64 t; cvta.to.shared.u64 t, %1; cvt.u32.u64 %0, t; }"
        : "=r"(a) : "l"(p));
    return a;
}
// pack two fp32 -> fp16x2 (lo = first arg in memory order)
__device__ __forceinline__ uint32_t pack_h(float lo, float hi) {
    uint32_t r;
    asm("cvt.rn.f16x2.f32 %0, %1, %2;" : "=r"(r) : "f"(hi), "f"(lo));
    return r;
}
__device__ __forceinline__ void mma16(float* d, const uint32_t* a, const uint32_t* b) {
    asm volatile(
        "mma.sync.aligned.m16n8k16.row.col.f32.f16.f16.f32 "
        "{%0,%1,%2,%3}, {%4,%5,%6,%7}, {%8,%9}, {%0,%1,%2,%3};"
        : "+f"(d[0]), "+f"(d[1]), "+f"(d[2]), "+f"(d[3])
        : "r"(a[0]), "r"(a[1]), "r"(a[2]), "r"(a[3]), "r"(b[0]), "r"(b[1]));
}
__device__ __forceinline__ void ldsm4(uint32_t* r, uint32_t addr) {
    asm volatile("ldmatrix.sync.aligned.m8n8.x4.shared.b16 {%0,%1,%2,%3}, [%4];"
        : "=r"(r[0]), "=r"(r[1]), "=r"(r[2]), "=r"(r[3]) : "r"(addr));
}
// paired exp2 in fp16 (1 MUFU op for 2 scores), returns fp32 pair
__device__ __forceinline__ float2 exp2_pair(float s0, float s1) {
    uint32_t h;
    asm("cvt.rn.f16x2.f32 %0, %1, %2;" : "=r"(h) : "f"(s1), "f"(s0));
    asm("ex2.approx.f16x2 %0, %0;" : "+r"(h));
    __half2 e = *reinterpret_cast<__half2*>(&h);
    return __half22float2(e);
}
#define CP_ASYNC16(s, g) \
    asm volatile("cp.async.cg.shared.global [%0], [%1], 16;" \
                 :: "r"(s), "l"(g) : "memory")
#define CP_COMMIT() asm volatile("cp.async.commit_group;" ::: "memory")
template<int N> __device__ __forceinline__ void cp_wait() {
    asm volatile("cp.async.wait_group %0;" :: "n"(N) : "memory");
}

// ---------------- converters / prep ----------------
__global__ void f2h_acts_kernel(
    const float4* __restrict__ a0, const float4* __restrict__ a1,
    const float4* __restrict__ a2,
    uint2* __restrict__ o0, uint2* __restrict__ o1, uint2* __restrict__ o2, int n4)
{
    int i = blockIdx.x * blockDim.x + threadIdx.x;
    if (i >= n4) return;
    const float4* in = blockIdx.y == 0 ? a0 : blockIdx.y == 1 ? a1 : a2;
    uint2* out       = blockIdx.y == 0 ? o0 : blockIdx.y == 1 ? o1 : o2;
    float4 f = in[i];
    out[i] = make_uint2(pack_h(f.x, f.y), pack_h(f.z, f.w));
}
__global__ void f2h_w_kernel(
    const float4* __restrict__ a0, const float4* __restrict__ a1,
    const float4* __restrict__ a2, const float4* __restrict__ a3,
    uint2* __restrict__ o0, uint2* __restrict__ o1,
    uint2* __restrict__ o2, uint2* __restrict__ o3, int n4)
{
    int i = blockIdx.x * blockDim.x + threadIdx.x;
    if (i >= n4) return;
    const float4* in = blockIdx.y == 0 ? a0 : blockIdx.y == 1 ? a1
                     : blockIdx.y == 2 ? a2 : a3;
    uint2* out       = blockIdx.y == 0 ? o0 : blockIdx.y == 1 ? o1
                     : blockIdx.y == 2 ? o2 : o3;
    float4 f = in[i];
    out[i] = make_uint2(pack_h(f.x, f.y), pack_h(f.z, f.w));
}
__global__ void transpose_w_kernel(const __half* __restrict__ src,
                                   __half* __restrict__ dst)
{
    __shared__ __half tile[32][33];
    const int l = blockIdx.z;
    const __half* s = src + (size_t)l * D2;
    __half* d = dst + (size_t)l * D2;
    const int x = blockIdx.x * 32 + threadIdx.x;
    const int y0 = blockIdx.y * 32;
    #pragma unroll
    for (int i = threadIdx.y; i < 32; i += 8)
        tile[i][threadIdx.x] = s[(size_t)(y0 + i) * DIM + x];
    __syncthreads();
    const int x2 = blockIdx.y * 32 + threadIdx.x;
    const int y2 = blockIdx.x * 32;
    #pragma unroll
    for (int i = threadIdx.y; i < 32; i += 8)
        d[(size_t)(y2 + i) * DIM + x2] = tile[threadIdx.x][i];
}
__global__ void biasfold_kernel(
    const float* __restrict__ Wk, const float* __restrict__ Wv,
    const float* __restrict__ bk, const float* __restrict__ bv,
    const float* __restrict__ bo, float* __restrict__ bkv)
{
    const int z = blockIdx.y;
    const int n = blockIdx.x * 128 + threadIdx.x;
    const int li = (z < 2) ? 1 : 2;
    const float* W  = ((z & 1) == 0 ? Wk : Wv) + (size_t)li * D2 + (size_t)n * DIM;
    const float* bs = ((z & 1) == 0 ? bk : bv) + li * DIM;
    const float* bsrc = bo + (li - 1) * DIM;
    float acc = 0.f;
    #pragma unroll 8
    for (int j = 0; j < DIM; j++) acc += W[j] * bsrc[j];
    bkv[z * DIM + n] = acc + bs[n];
}

// ---------------- GEMM core (fp16, ldmatrix, 3-stage) ----------------
#define GPADW 20
#define GSLOTW (128*GPADW)
#define GSTG 3
#define GEMM_SMEM ((128 + GSTG*2*GSLOTW) * 4)   // 61952 B

struct GemmAcc { float a[2][8][4]; };

__device__ __forceinline__ void gemm_mainloop(
    const __half* __restrict__ X, const __half* __restrict__ W,
    const float* __restrict__ bias, float* sBias, uint32_t* sT,
    int m0, int n0, int tid, GemmAcc& A)
{
    const uint32_t tAddr = smem_u32(sT);
    const int lane = tid & 31, wid = tid >> 5;
    const int wm = wid & 3, wn = wid >> 2;
    const int j  = lane >> 3, r7 = lane & 7;
    const int aRow = (j & 1) * 8 + r7, aCol = (j >> 1) * 4;
    const int bRow = (j >> 1) * 8 + r7, bCol = (j & 1) * 4;

    if (tid < 128) sBias[tid] = bias[n0 + tid];

    #pragma unroll
    for (int mt = 0; mt < 2; mt++)
        #pragma unroll
        for (int nt = 0; nt < 8; nt++)
            #pragma unroll
            for (int i = 0; i < 4; i++) A.a[mt][nt][i] = 0.f;

    auto load_chunk = [&](int c) {
        const uint32_t base = tAddr + (uint32_t)(c % GSTG) * (2 * GSLOTW * 4);
        const __half* gA = X + (size_t)m0 * DIM + c * 32;
        const __half* gB = W + (size_t)n0 * DIM + c * 32;
        #pragma unroll
        for (int i = 0; i < 2; i++) {
            int idx = tid + i * 256;
            int row = idx >> 2, f = idx & 3;
            uint32_t d = base + (uint32_t)(row * GPADW + f * 4) * 4;
            const size_t go = (size_t)row * DIM + f * 8;
            CP_ASYNC16(d, gA + go);
            CP_ASYNC16(d + GSLOTW * 4, gB + go);
        }
        CP_COMMIT();
    };

    load_chunk(0);
    load_chunk(1);
    for (int c = 0; c < 24; c++) {
        if (c < 23) cp_wait<1>(); else cp_wait<0>();
        __syncthreads();
        if (c + 2 < 24) load_chunk(c + 2);

        const uint32_t aB = tAddr + (uint32_t)(c % GSTG) * (2 * GSLOTW * 4);
        const uint32_t bB = aB + GSLOTW * 4;

        #pragma unroll
        for (int ks = 0; ks < 2; ks++) {
            uint32_t afr[2][4];
            #pragma unroll
            for (int mt = 0; mt < 2; mt++)
                ldsm4(afr[mt], aB + (uint32_t)((wm * 32 + mt * 16 + aRow) * GPADW
                                               + ks * 8 + aCol) * 4);
            uint32_t bfr[8][2];
            #pragma unroll
            for (int p = 0; p < 4; p++) {
                uint32_t rr[4];
                ldsm4(rr, bB + (uint32_t)((wn * 64 + p * 16 + bRow) * GPADW
                                          + ks * 8 + bCol) * 4);
                bfr[2*p][0]   = rr[0]; bfr[2*p][1]   = rr[1];
                bfr[2*p+1][0] = rr[2]; bfr[2*p+1][1] = rr[3];
            }
            #pragma unroll
            for (int nt = 0; nt < 8; nt++) {
                mma16(A.a[0][nt], afr[0], bfr[nt]);
                mma16(A.a[1][nt], afr[1], bfr[nt]);
            }
        }
    }
}

__global__ __launch_bounds__(256, 2) void gemm_qkv_kernel(
    const __half* __restrict__ xq, const __half* __restrict__ xk,
    const __half* __restrict__ xv,
    const __half* __restrict__ wq, const __half* __restrict__ wk,
    const __half* __restrict__ wv,
    const float* __restrict__ bq, const float* __restrict__ bk,
    const float* __restrict__ bv,
    __half* __restrict__ oq, __half* __restrict__ ok,
    __half* __restrict__ ovt, float qscale)
{
    extern __shared__ __align__(128) float smf[];
    float* sBias = smf;
    uint32_t* sT = (uint32_t*)(smf + 128);

    const int tid = threadIdx.x;
    const int slice = blockIdx.x / 6;
    const int n0 = (blockIdx.x % 6) * 128;
    const int m0 = blockIdx.y * 128;

    const __half* X = slice == 0 ? xq : slice == 1 ? xk : xv;
    const __half* W = slice == 0 ? wq : slice == 1 ? wk : wv;
    const float*  B = slice == 0 ? bq : slice == 1 ? bk : bv;

    GemmAcc A;
    gemm_mainloop(X, W, B, sBias, sT, m0, n0, tid, A);

    const int lane = tid & 31, wid = tid >> 5;
    const int g = lane >> 2, t = lane & 3;
    const int wm = wid & 3, wn = wid >> 2;
    const float scale = slice == 0 ? qscale : 1.0f;

    #pragma unroll
    for (int mt = 0; mt < 2; mt++) {
        const int m = m0 + wm * 32 + mt * 16 + g;
        #pragma unroll
        for (int nt = 0; nt < 8; nt++) {
            const int nl = wn * 64 + nt * 8 + 2 * t;
            float v0x = (A.a[mt][nt][0] + sBias[nl])     * scale;
            float v0y = (A.a[mt][nt][1] + sBias[nl + 1]) * scale;
            float v1x = (A.a[mt][nt][2] + sBias[nl])     * scale;
            float v1y = (A.a[mt][nt][3] + sBias[nl + 1]) * scale;
            if (slice < 2) {
                __half* ob = slice == 0 ? oq : ok;
                *(uint32_t*)(ob + (size_t)m * DIM + n0 + nl)       = pack_h(v0x, v0y);
                *(uint32_t*)(ob + (size_t)(m + 8) * DIM + n0 + nl) = pack_h(v1x, v1y);
            } else {
                const int n = n0 + nl;
                const size_t rb = (size_t)((m >> 10) * 768);
                const int s = m & (SEQ - 1);
                ovt[(rb + n)     * SEQ + s]     = __float2half(v0x);
                ovt[(rb + n + 1) * SEQ + s]     = __float2half(v0y);
                ovt[(rb + n)     * SEQ + s + 8] = __float2half(v1x);
                ovt[(rb + n + 1) * SEQ + s + 8] = __float2half(v1y);
            }
        }
    }
}

__global__ __launch_bounds__(256, 2) void fold_gemm_kernel(
    const __half* __restrict__ wk, const __half* __restrict__ wv,
    const __half* __restrict__ woT, const float* __restrict__ zero,
    __half* __restrict__ wkv)
{
    extern __shared__ __align__(128) float smf[];
    float* sBias = smf;
    uint32_t* sT = (uint32_t*)(smf + 128);

    const int tid = threadIdx.x;
    const int n0 = blockIdx.x * 128;
    const int m0 = blockIdx.y * 128;
    const int z  = blockIdx.z;
    const int li = (z < 2) ? 1 : 2;

    const __half* A = ((z & 1) == 0 ? wk : wv) + (size_t)li * D2;
    const __half* W = woT + (size_t)(li - 1) * D2;
    __half* O = wkv + (size_t)z * D2;

    GemmAcc Ac;
    gemm_mainloop(A, W, zero, sBias, sT, m0, n0, tid, Ac);

    const int lane = tid & 31, wid = tid >> 5;
    const int g = lane >> 2, t = lane & 3;
    const int wm = wid & 3, wn = wid >> 2;

    #pragma unroll
    for (int mt = 0; mt < 2; mt++) {
        const int m = m0 + wm * 32 + mt * 16 + g;
        #pragma unroll
        for (int nt = 0; nt < 8; nt++) {
            const int nl = wn * 64 + nt * 8 + 2 * t;
            *(uint32_t*)(O + (size_t)m * DIM + n0 + nl) =
                pack_h(Ac.a[mt][nt][0], Ac.a[mt][nt][1]);
            *(uint32_t*)(O + (size_t)(m + 8) * DIM + n0 + nl) =
                pack_h(Ac.a[mt][nt][2], Ac.a[mt][nt][3]);
        }
    }
}

__global__ __launch_bounds__(256, 2) void gemm_ofin_kernel(
    const __half* __restrict__ X, const __half* __restrict__ W,
    const float* __restrict__ bias, const float* __restrict__ add,
    float* __restrict__ out)
{
    extern __shared__ __align__(128) float smf[];
    float* sBias = smf;
    uint32_t* sT = (uint32_t*)(smf + 128);

    const int tid = threadIdx.x;
    const int n0 = blockIdx.x * 128;
    const int m0 = blockIdx.y * 128;

    GemmAcc A;
    gemm_mainloop(X, W, bias, sBias, sT, m0, n0, tid, A);

    const int lane = tid & 31, wid = tid >> 5;
    const int g = lane >> 2, t = lane & 3;
    const int wm = wid & 3, wn = wid >> 2;

    #pragma unroll
    for (int mt = 0; mt < 2; mt++) {
        const int m = m0 + wm * 32 + mt * 16 + g;
        #pragma unroll
        for (int nt = 0; nt < 8; nt++) {
            const int nl = wn * 64 + nt * 8 + 2 * t;
            const size_t o0 = (size_t)m * DIM + n0 + nl;
            const size_t o1 = (size_t)(m + 8) * DIM + n0 + nl;
            float2 a0 = *reinterpret_cast<const float2*>(add + o0);
            float2 a1 = *reinterpret_cast<const float2*>(add + o1);
            *reinterpret_cast<float2*>(out + o0) =
                make_float2(A.a[mt][nt][0] + sBias[nl] + a0.x,
                            A.a[mt][nt][1] + sBias[nl + 1] + a0.y);
            *reinterpret_cast<float2*>(out + o1) =
                make_float2(A.a[mt][nt][2] + sBias[nl] + a1.x,
                            A.a[mt][nt][3] + sBias[nl + 1] + a1.y);
        }
    }
}

// ---------------- fp16 flash attention (register-resident P) ----------------
#define APW 36
#define KV_SLOTW (64*APW*2)
#define ASTG 3
#define QP_OFFW  (ASTG*KV_SLOTW)
#define ATTN_SMEM ((ASTG*KV_SLOTW + 128*APW) * 4)   // 73728 B

__global__ __launch_bounds__(256, 2) void attn_h_kernel(
    const __half* __restrict__ q, const __half* __restrict__ k,
    const __half* __restrict__ vt, const float* __restrict__ dist,
    __half* __restrict__ ctx)
{
    extern __shared__ __align__(128) uint32_t smw[];
    const uint32_t base = smem_u32(smw);
    uint32_t* sQP = smw + QP_OFFW;

    const int tid  = threadIdx.x;
    const int lane = tid & 31, wid = tid >> 5;
    const int g = lane >> 2, t = lane & 3;
    const int j  = lane >> 3, r7 = lane & 7;
    const int bRow = (j >> 1) * 8 + r7, bCol = (j & 1) * 4;

    const int b = blockIdx.z, h = blockIdx.y;
    const int q0 = blockIdx.x * 128;

    const __half* qb = q + (size_t)b * SEQ * DIM + h * DKH;
    const __half* kb = k + (size_t)b * SEQ * DIM + h * DKH;
    const __half* vb = vt + ((size_t)b * 768 + h * DKH) * SEQ;
    const float* db = dist + (size_t)b * SEQ * SEQ;

    const int qi0 = q0 + wid * 16 + g;
    const int qi1 = qi0 + 8;

    auto load_kv = [&](int kt) {
        const uint32_t dst = base + (uint32_t)(kt % ASTG) * (KV_SLOTW * 4);
        const __half* gk = kb + (size_t)kt * 64 * DIM;
        const __half* gv = vb + kt * 64;
        #pragma unroll
        for (int i = 0; i < 2; i++) {
            int idx = tid + i * 256;
            int row = idx >> 3, f = idx & 7;
            CP_ASYNC16(dst + (uint32_t)(row * APW + f * 4) * 4,
                       gk + (size_t)row * DIM + f * 8);
            CP_ASYNC16(dst + (uint32_t)(64 * APW + row * APW + f * 4) * 4,
                       gv + (size_t)row * SEQ + f * 8);
        }
        CP_COMMIT();
    };

    // prologue: Q load overlapped with kv0/kv1 loads
    {
        const uint32_t qdst = base + QP_OFFW * 4;
        #pragma unroll
        for (int i = 0; i < 4; i++) {
            int idx = tid + i * 256;
            int row = idx >> 3, f = idx & 7;
            CP_ASYNC16(qdst + (uint32_t)(row * APW + f * 4) * 4,
                       qb + (size_t)(q0 + row) * DIM + f * 8);
        }
        CP_COMMIT();
    }
    load_kv(0);
    load_kv(1);
    cp_wait<2>();           // Q retired; kv0/kv1 still in flight
    __syncthreads();

    uint32_t qf[4][4];
    {
        const uint32_t* qp0 = sQP + (wid * 16 + g) * APW;
        const uint32_t* qp1 = qp0 + 8 * APW;
        #pragma unroll
        for (int ks = 0; ks < 4; ks++) {
            qf[ks][0] = qp0[ks * 8 + t];
            qf[ks][1] = qp1[ks * 8 + t];
            qf[ks][2] = qp0[ks * 8 + t + 4];
            qf[ks][3] = qp1[ks * 8 + t + 4];
        }
    }

    float Of[8][4];
    #pragma unroll
    for (int nt = 0; nt < 8; nt++)
        #pragma unroll
        for (int i = 0; i < 4; i++) Of[nt][i] = 0.f;
    float m_run0 = -1e30f, m_run1 = -1e30f, z_run0 = 0.f, z_run1 = 0.f;

    for (int kt = 0; kt < 16; kt++) {
        if (kt < 15) cp_wait<1>(); else cp_wait<0>();
        __syncthreads();
        if (kt + 2 < 16) load_kv(kt + 2);

        const uint32_t ksAddr = base + (uint32_t)(kt % ASTG) * (KV_SLOTW * 4);
        const uint32_t vsAddr = ksAddr + 64 * APW * 4;
        const int kbase = kt * 64;

        // ---- S = Q K^T ----
        float Sf[8][4];
        #pragma unroll
        for (int nt = 0; nt < 8; nt++)
            #pragma unroll
            for (int i = 0; i < 4; i++) Sf[nt][i] = 0.f;
        #pragma unroll
        for (int ks = 0; ks < 4; ks++) {
            uint32_t kf[8][2];
            #pragma unroll
            for (int p = 0; p < 4; p++) {
                uint32_t rr[4];
                ldsm4(rr, ksAddr + (uint32_t)((p * 16 + bRow) * APW
                                              + ks * 8 + bCol) * 4);
                kf[2*p][0]   = rr[0]; kf[2*p][1]   = rr[1];
                kf[2*p+1][0] = rr[2]; kf[2*p+1][1] = rr[3];
            }
            #pragma unroll
            for (int nt = 0; nt < 8; nt++)
                mma16(Sf[nt], qf[ks], kf[nt]);
        }

        // ---- online softmax ----
        float mloc0 = -1e30f, mloc1 = -1e30f;
        #pragma unroll
        for (int nt = 0; nt < 8; nt++) {
            mloc0 = fmaxf(mloc0, fmaxf(Sf[nt][0], Sf[nt][1]));
            mloc1 = fmaxf(mloc1, fmaxf(Sf[nt][2], Sf[nt][3]));
        }
        #pragma unroll
        for (int off = 1; off <= 2; off <<= 1) {
            mloc0 = fmaxf(mloc0, __shfl_xor_sync(0xffffffffu, mloc0, off));
            mloc1 = fmaxf(mloc1, __shfl_xor_sync(0xffffffffu, mloc1, off));
        }
        const float mnew0 = fmaxf(m_run0, mloc0);
        const float mnew1 = fmaxf(m_run1, mloc1);
        const float f0 = exp2f(m_run0 - mnew0);
        const float f1 = exp2f(m_run1 - mnew1);
        z_run0 *= f0; z_run1 *= f1;
        #pragma unroll
        for (int nt = 0; nt < 8; nt++) {
            Of[nt][0] *= f0; Of[nt][1] *= f0;
            Of[nt][2] *= f1; Of[nt][3] *= f1;
        }

        // ---- exp + mask -> P kept in registers (== PV A-fragments) ----
        float zs0 = 0.f, zs1 = 0.f;
        uint32_t Pr0[8], Pr1[8];
        #pragma unroll
        for (int h2 = 0; h2 < 2; h2++) {
            float2 md0[4], md1[4];
            #pragma unroll
            for (int jj = 0; jj < 4; jj++) {
                const int nt = h2 * 4 + jj;
                const int ki = kbase + nt * 8 + 2 * t;
                md0[jj] = *reinterpret_cast<const float2*>(
                    db + (size_t)qi0 * SEQ + ki);
                md1[jj] = *reinterpret_cast<const float2*>(
                    db + (size_t)qi1 * SEQ + ki);
                if (qi0 == ki)     md0[jj].x += 1.f;
                if (qi0 == ki + 1) md0[jj].y += 1.f;
                if (qi1 == ki)     md1[jj].x += 1.f;
                if (qi1 == ki + 1) md1[jj].y += 1.f;
            }
            #pragma unroll
            for (int jj = 0; jj < 4; jj++) {
                const int nt = h2 * 4 + jj;
                float2 e01 = exp2_pair(Sf[nt][0] - mnew0, Sf[nt][1] - mnew0);
                float2 e23 = exp2_pair(Sf[nt][2] - mnew1, Sf[nt][3] - mnew1);
                zs0 += e01.x + e01.y;
                zs1 += e23.x + e23.y;
                Pr0[nt] = pack_h(e01.x * md0[jj].x, e01.y * md0[jj].y);
                Pr1[nt] = pack_h(e23.x * md1[jj].x, e23.y * md1[jj].y);
            }
        }
        #pragma unroll
        for (int off = 1; off <= 2; off <<= 1) {
            zs0 += __shfl_xor_sync(0xffffffffu, zs0, off);
            zs1 += __shfl_xor_sync(0xffffffffu, zs1, off);
        }
        z_run0 += zs0; z_run1 += zs1;
        m_run0 = mnew0; m_run1 = mnew1;

        // ---- O += P V directly from registers ----
        #pragma unroll
        for (int ks = 0; ks < 4; ks++) {
            uint32_t af[4] = { Pr0[2*ks], Pr1[2*ks], Pr0[2*ks+1], Pr1[2*ks+1] };
            uint32_t vf[8][2];
            #pragma unroll
            for (int p = 0; p < 4; p++) {
                uint32_t rr[4];
                ldsm4(rr, vsAddr + (uint32_t)((p * 16 + bRow) * APW
                                              + ks * 8 + bCol) * 4);
                vf[2*p][0]   = rr[0]; vf[2*p][1]   = rr[1];
                vf[2*p+1][0] = rr[2]; vf[2*p+1][1] = rr[3];
            }
            #pragma unroll
            for (int nt = 0; nt < 8; nt++)
                mma16(Of[nt], af, vf[nt]);
        }
    }

    const float inv0 = 1.f / z_run0, inv1 = 1.f / z_run1;
    #pragma unroll
    for (int nt = 0; nt < 8; nt++) {
        const int d = h * DKH + nt * 8 + 2 * t;
        *(uint32_t*)(ctx + ((size_t)b * SEQ + qi0) * DIM + d) =
            pack_h(Of[nt][0] * inv0, Of[nt][1] * inv0);
        *(uint32_t*)(ctx + ((size_t)b * SEQ + qi1) * DIM + d) =
            pack_h(Of[nt][2] * inv1, Of[nt][3] * inv1);
    }
}

// ---------------- host ----------------
extern "C" void kernel_launch(void* const* d_in, const int* in_sizes, int n_in,
                              void* d_out, int out_size)
{
    const float* Q    = (const float*)d_in[0];
    const float* Kin  = (const float*)d_in[1];
    const float* Vin  = (const float*)d_in[2];
    const float* dist = (const float*)d_in[3];
    const float* Wq   = (const float*)d_in[4];
    const float* bq   = (const float*)d_in[5];
    const float* Wk   = (const float*)d_in[6];
    const float* bk   = (const float*)d_in[7];
    const float* Wv   = (const float*)d_in[8];
    const float* bv   = (const float*)d_in[9];
    const float* Wo   = (const float*)d_in[10];
    const float* bo   = (const float*)d_in[11];
    float* out = (float*)d_out;

    __half *qin, *kin, *vin, *qh, *kh, *vtb, *ctxb;
    __half *wqh, *wkh, *wvh, *woh, *woT, *wkv;
    float *bkv, *zero;
    cudaGetSymbolAddress((void**)&qin,  g_qin);
    cudaGetSymbolAddress((void**)&kin,  g_kin);
    cudaGetSymbolAddress((void**)&vin,  g_vin);
    cudaGetSymbolAddress((void**)&qh,   g_qh);
    cudaGetSymbolAddress((void**)&kh,   g_kh);
    cudaGetSymbolAddress((void**)&vtb,  g_vt);
    cudaGetSymbolAddress((void**)&ctxb, g_ctx);
    cudaGetSymbolAddress((void**)&wqh,  g_wq);
    cudaGetSymbolAddress((void**)&wkh,  g_wk);
    cudaGetSymbolAddress((void**)&wvh,  g_wv);
    cudaGetSymbolAddress((void**)&woh,  g_wo);
    cudaGetSymbolAddress((void**)&woT,  g_woT);
    cudaGetSymbolAddress((void**)&wkv,  g_wkv);
    cudaGetSymbolAddress((void**)&bkv,  g_bkv);
    cudaGetSymbolAddress((void**)&zero, g_zero);

    cudaFuncSetAttribute(gemm_qkv_kernel,
                         cudaFuncAttributeMaxDynamicSharedMemorySize, GEMM_SMEM);
    cudaFuncSetAttribute(fold_gemm_kernel,
                         cudaFuncAttributeMaxDynamicSharedMemorySize, GEMM_SMEM);
    cudaFuncSetAttribute(gemm_ofin_kernel,
                         cudaFuncAttributeMaxDynamicSharedMemorySize, GEMM_SMEM);
    cudaFuncSetAttribute(attn_h_kernel,
                         cudaFuncAttributeMaxDynamicSharedMemorySize, ATTN_SMEM);

    {
        const int nAct4 = MTOT * DIM / 4;
        const int nW4   = NL * D2 / 4;
        dim3 ga((nAct4 + 255) / 256, 3);
        f2h_acts_kernel<<<ga, 256>>>((const float4*)Q, (const float4*)Kin,
                                     (const float4*)Vin,
                                     (uint2*)qin, (uint2*)kin, (uint2*)vin, nAct4);
        dim3 gw((nW4 + 255) / 256, 4);
        f2h_w_kernel<<<gw, 256>>>((const float4*)Wq, (const float4*)Wk,
                                  (const float4*)Wv, (const float4*)Wo,
                                  (uint2*)wqh, (uint2*)wkh, (uint2*)wvh, (uint2*)woh, nW4);
        dim3 gt(24, 24, 2);
        transpose_w_kernel<<<gt, dim3(32, 8)>>>(woh, woT);
        dim3 gf(6, 6, 4);
        fold_gemm_kernel<<<gf, 256, GEMM_SMEM>>>(wkh, wvh, woT, zero, wkv);
        dim3 gb(6, 4);
        biasfold_kernel<<<gb, 128>>>(Wk, Wv, bk, bv, bo, bkv);
    }

    const float qscale = 0.125f * 1.4426950408889634f;  // log2(e)/sqrt(64)
    dim3 qkvgrid(18, MTOT / 128);
    dim3 ogrid(DIM / 128, MTOT / 128);
    dim3 agrid(SEQ / 128, NH, BSZ);

    // layer 1
    gemm_qkv_kernel<<<qkvgrid, 256, GEMM_SMEM>>>(
        qin, kin, vin, wqh, wkh, wvh, bq, bk, bv, qh, kh, vtb, qscale);
    attn_h_kernel<<<agrid, 256, ATTN_SMEM>>>(qh, kh, vtb, dist, ctxb);
    // layer 2 (folded K/V from ctx)
    gemm_qkv_kernel<<<qkvgrid, 256, GEMM_SMEM>>>(
        qin, ctxb, ctxb, wqh + D2, wkv, wkv + D2,
        bq + DIM, bkv, bkv + DIM, qh, kh, vtb, qscale);
    attn_h_kernel<<<agrid, 256, ATTN_SMEM>>>(qh, kh, vtb, dist, ctxb);
    // layer 3 (folded)
    gemm_qkv_kernel<<<qkvgrid, 256, GEMM_SMEM>>>(
        qin, ctxb, ctxb, wqh + 2 * (size_t)D2, wkv + 2 * (size_t)D2, wkv + 3 * (size_t)D2,
        bq + 2 * DIM, bkv + 2 * DIM, bkv + 3 * DIM, qh, kh, vtb, qscale);
    attn_h_kernel<<<agrid, 256, ATTN_SMEM>>>(qh, kh, vtb, dist, ctxb);
    // final
    gemm_ofin_kernel<<<ogrid, 256, GEMM_SMEM>>>(ctxb, woh + 2 * (size_t)D2,
                                                bo + 2 * DIM, Vin, out);
}

// round 16
// speedup vs baseline: 1.1504x; 1.0411x over previous
#include <cuda_runtime.h>
#include <cuda_fp16.h>
#include <cstdint>
#include <math.h>

#define BSZ 8
#define SEQ 1024
#define DIM 768
#define NH  12
#define DKH 64
#define NL  3
#define MTOT (BSZ*SEQ)
#define D2   (DIM*DIM)

__device__ __half g_qin [MTOT*DIM];
__device__ __half g_kin [MTOT*DIM];
__device__ __half g_vin [MTOT*DIM];
__device__ __half g_qh  [MTOT*DIM];
__device__ __half g_kh  [MTOT*DIM];
__device__ __half g_vt  [MTOT*DIM];   // V transposed per (b): [(b*768+d)][SEQ]
__device__ __half g_ctx [MTOT*DIM];
__device__ __half g_wq  [NL*D2];
__device__ __half g_wk  [NL*D2];
__device__ __half g_wv  [NL*D2];
__device__ __half g_wo  [NL*D2];
__device__ __half g_woT [2*D2];       // Wo^T of layers 0,1
__device__ __half g_wkv [4*D2];       // folded Wk1Wo0, Wv1Wo0, Wk2Wo1, Wv2Wo1
__device__ float  g_bkv [4*DIM];
__device__ float  g_zero[DIM];        // zero-initialized
__device__ __half g_dmh [BSZ*SEQ*SEQ]; // dist in fp16 (mask; diag added in-kernel)

__device__ __forceinline__ uint32_t smem_u32(const void* p) {
    uint32_t a;
    asm("{ .reg .u64 t; cvta.to.shared.u64 t, %1; cvt.u32.u64 %0, t; }"
        : "=r"(a) : "l"(p));
    return a;
}
// pack two fp32 -> fp16x2 (lo = first arg in memory order)
__device__ __forceinline__ uint32_t pack_h(float lo, float hi) {
    uint32_t r;
    asm("cvt.rn.f16x2.f32 %0, %1, %2;" : "=r"(r) : "f"(hi), "f"(lo));
    return r;
}
__device__ __forceinline__ void mma16(float* d, const uint32_t* a, const uint32_t* b) {
    asm volatile(
        "mma.sync.aligned.m16n8k16.row.col.f32.f16.f16.f32 "
        "{%0,%1,%2,%3}, {%4,%5,%6,%7}, {%8,%9}, {%0,%1,%2,%3};"
        : "+f"(d[0]), "+f"(d[1]), "+f"(d[2]), "+f"(d[3])
        : "r"(a[0]), "r"(a[1]), "r"(a[2]), "r"(a[3]), "r"(b[0]), "r"(b[1]));
}
__device__ __forceinline__ void ldsm4(uint32_t* r, uint32_t addr) {
    asm volatile("ldmatrix.sync.aligned.m8n8.x4.shared.b16 {%0,%1,%2,%3}, [%4];"
        : "=r"(r[0]), "=r"(r[1]), "=r"(r[2]), "=r"(r[3]) : "r"(addr));
}
// paired exp2 in fp16 (1 MUFU op for 2 scores), returns fp32 pair
__device__ __forceinline__ float2 exp2_pair(float s0, float s1) {
    uint32_t h;
    asm("cvt.rn.f16x2.f32 %0, %1, %2;" : "=r"(h) : "f"(s1), "f"(s0));
    asm("ex2.approx.f16x2 %0, %0;" : "+r"(h));
    __half2 e = *reinterpret_cast<__half2*>(&h);
    return __half22float2(e);
}
#define CP_ASYNC16(s, g) \
    asm volatile("cp.async.cg.shared.global [%0], [%1], 16;" \
                 :: "r"(s), "l"(g) : "memory")
#define CP_COMMIT() asm volatile("cp.async.commit_group;" ::: "memory")
template<int N> __device__ __forceinline__ void cp_wait() {
    asm volatile("cp.async.wait_group %0;" :: "n"(N) : "memory");
}

// ---------------- converters / prep ----------------
__global__ void f2h_acts_kernel(
    const float4* __restrict__ a0, const float4* __restrict__ a1,
    const float4* __restrict__ a2,
    uint2* __restrict__ o0, uint2* __restrict__ o1, uint2* __restrict__ o2, int n4)
{
    int i = blockIdx.x * blockDim.x + threadIdx.x;
    if (i >= n4) return;
    const float4* in = blockIdx.y == 0 ? a0 : blockIdx.y == 1 ? a1 : a2;
    uint2* out       = blockIdx.y == 0 ? o0 : blockIdx.y == 1 ? o1 : o2;
    float4 f = in[i];
    out[i] = make_uint2(pack_h(f.x, f.y), pack_h(f.z, f.w));
}
__global__ void f2h_w_kernel(
    const float4* __restrict__ a0, const float4* __restrict__ a1,
    const float4* __restrict__ a2, const float4* __restrict__ a3,
    uint2* __restrict__ o0, uint2* __restrict__ o1,
    uint2* __restrict__ o2, uint2* __restrict__ o3, int n4)
{
    int i = blockIdx.x * blockDim.x + threadIdx.x;
    if (i >= n4) return;
    const float4* in = blockIdx.y == 0 ? a0 : blockIdx.y == 1 ? a1
                     : blockIdx.y == 2 ? a2 : a3;
    uint2* out       = blockIdx.y == 0 ? o0 : blockIdx.y == 1 ? o1
                     : blockIdx.y == 2 ? o2 : o3;
    float4 f = in[i];
    out[i] = make_uint2(pack_h(f.x, f.y), pack_h(f.z, f.w));
}
__global__ void f2h_dist_kernel(const float4* __restrict__ in,
                                uint2* __restrict__ out, int n4)
{
    int i = blockIdx.x * blockDim.x + threadIdx.x;
    if (i >= n4) return;
    float4 f = in[i];
    out[i] = make_uint2(pack_h(f.x, f.y), pack_h(f.z, f.w));
}
__global__ void transpose_w_kernel(const __half* __restrict__ src,
                                   __half* __restrict__ dst)
{
    __shared__ __half tile[32][33];
    const int l = blockIdx.z;
    const __half* s = src + (size_t)l * D2;
    __half* d = dst + (size_t)l * D2;
    const int x = blockIdx.x * 32 + threadIdx.x;
    const int y0 = blockIdx.y * 32;
    #pragma unroll
    for (int i = threadIdx.y; i < 32; i += 8)
        tile[i][threadIdx.x] = s[(size_t)(y0 + i) * DIM + x];
    __syncthreads();
    const int x2 = blockIdx.y * 32 + threadIdx.x;
    const int y2 = blockIdx.x * 32;
    #pragma unroll
    for (int i = threadIdx.y; i < 32; i += 8)
        d[(size_t)(y2 + i) * DIM + x2] = tile[threadIdx.x][i];
}
__global__ void biasfold_kernel(
    const float* __restrict__ Wk, const float* __restrict__ Wv,
    const float* __restrict__ bk, const float* __restrict__ bv,
    const float* __restrict__ bo, float* __restrict__ bkv)
{
    const int z = blockIdx.y;
    const int n = blockIdx.x * 128 + threadIdx.x;
    const int li = (z < 2) ? 1 : 2;
    const float* W  = ((z & 1) == 0 ? Wk : Wv) + (size_t)li * D2 + (size_t)n * DIM;
    const float* bs = ((z & 1) == 0 ? bk : bv) + li * DIM;
    const float* bsrc = bo + (li - 1) * DIM;
    float acc = 0.f;
    #pragma unroll 8
    for (int j = 0; j < DIM; j++) acc += W[j] * bsrc[j];
    bkv[z * DIM + n] = acc + bs[n];
}

// ---------------- GEMM core (fp16, ldmatrix, 3-stage) ----------------
#define GPADW 20
#define GSLOTW (128*GPADW)
#define GSTG 3
#define GEMM_SMEM ((128 + GSTG*2*GSLOTW) * 4)   // 61952 B

struct GemmAcc { float a[2][8][4]; };

__device__ __forceinline__ void gemm_mainloop(
    const __half* __restrict__ X, const __half* __restrict__ W,
    const float* __restrict__ bias, float* sBias, uint32_t* sT,
    int m0, int n0, int tid, GemmAcc& A)
{
    const uint32_t tAddr = smem_u32(sT);
    const int lane = tid & 31, wid = tid >> 5;
    const int wm = wid & 3, wn = wid >> 2;
    const int j  = lane >> 3, r7 = lane & 7;
    const int aRow = (j & 1) * 8 + r7, aCol = (j >> 1) * 4;
    const int bRow = (j >> 1) * 8 + r7, bCol = (j & 1) * 4;

    if (tid < 128) sBias[tid] = bias[n0 + tid];

    #pragma unroll
    for (int mt = 0; mt < 2; mt++)
        #pragma unroll
        for (int nt = 0; nt < 8; nt++)
            #pragma unroll
            for (int i = 0; i < 4; i++) A.a[mt][nt][i] = 0.f;

    auto load_chunk = [&](int c) {
        const uint32_t base = tAddr + (uint32_t)(c % GSTG) * (2 * GSLOTW * 4);
        const __half* gA = X + (size_t)m0 * DIM + c * 32;
        const __half* gB = W + (size_t)n0 * DIM + c * 32;
        #pragma unroll
        for (int i = 0; i < 2; i++) {
            int idx = tid + i * 256;
            int row = idx >> 2, f = idx & 3;
            uint32_t d = base + (uint32_t)(row * GPADW + f * 4) * 4;
            const size_t go = (size_t)row * DIM + f * 8;
            CP_ASYNC16(d, gA + go);
            CP_ASYNC16(d + GSLOTW * 4, gB + go);
        }
        CP_COMMIT();
    };

    load_chunk(0);
    load_chunk(1);
    for (int c = 0; c < 24; c++) {
        if (c < 23) cp_wait<1>(); else cp_wait<0>();
        __syncthreads();
        if (c + 2 < 24) load_chunk(c + 2);

        const uint32_t aB = tAddr + (uint32_t)(c % GSTG) * (2 * GSLOTW * 4);
        const uint32_t bB = aB + GSLOTW * 4;

        #pragma unroll
        for (int ks = 0; ks < 2; ks++) {
            uint32_t afr[2][4];
            #pragma unroll
            for (int mt = 0; mt < 2; mt++)
                ldsm4(afr[mt], aB + (uint32_t)((wm * 32 + mt * 16 + aRow) * GPADW
                                               + ks * 8 + aCol) * 4);
            uint32_t bfr[8][2];
            #pragma unroll
            for (int p = 0; p < 4; p++) {
                uint32_t rr[4];
                ldsm4(rr, bB + (uint32_t)((wn * 64 + p * 16 + bRow) * GPADW
                                          + ks * 8 + bCol) * 4);
                bfr[2*p][0]   = rr[0]; bfr[2*p][1]   = rr[1];
                bfr[2*p+1][0] = rr[2]; bfr[2*p+1][1] = rr[3];
            }
            #pragma unroll
            for (int nt = 0; nt < 8; nt++) {
                mma16(A.a[0][nt], afr[0], bfr[nt]);
                mma16(A.a[1][nt], afr[1], bfr[nt]);
            }
        }
    }
}

__global__ __launch_bounds__(256, 2) void gemm_qkv_kernel(
    const __half* __restrict__ xq, const __half* __restrict__ xk,
    const __half* __restrict__ xv,
    const __half* __restrict__ wq, const __half* __restrict__ wk,
    const __half* __restrict__ wv,
    const float* __restrict__ bq, const float* __restrict__ bk,
    const float* __restrict__ bv,
    __half* __restrict__ oq, __half* __restrict__ ok,
    __half* __restrict__ ovt, float qscale)
{
    extern __shared__ __align__(128) float smf[];
    float* sBias = smf;
    uint32_t* sT = (uint32_t*)(smf + 128);

    const int tid = threadIdx.x;
    const int slice = blockIdx.x / 6;
    const int n0 = (blockIdx.x % 6) * 128;
    const int m0 = blockIdx.y * 128;

    const __half* X = slice == 0 ? xq : slice == 1 ? xk : xv;
    const __half* W = slice == 0 ? wq : slice == 1 ? wk : wv;
    const float*  B = slice == 0 ? bq : slice == 1 ? bk : bv;

    GemmAcc A;
    gemm_mainloop(X, W, B, sBias, sT, m0, n0, tid, A);

    const int lane = tid & 31, wid = tid >> 5;
    const int g = lane >> 2, t = lane & 3;
    const int wm = wid & 3, wn = wid >> 2;
    const float scale = slice == 0 ? qscale : 1.0f;

    #pragma unroll
    for (int mt = 0; mt < 2; mt++) {
        const int m = m0 + wm * 32 + mt * 16 + g;
        #pragma unroll
        for (int nt = 0; nt < 8; nt++) {
            const int nl = wn * 64 + nt * 8 + 2 * t;
            float v0x = (A.a[mt][nt][0] + sBias[nl])     * scale;
            float v0y = (A.a[mt][nt][1] + sBias[nl + 1]) * scale;
            float v1x = (A.a[mt][nt][2] + sBias[nl])     * scale;
            float v1y = (A.a[mt][nt][3] + sBias[nl + 1]) * scale;
            if (slice < 2) {
                __half* ob = slice == 0 ? oq : ok;
                *(uint32_t*)(ob + (size_t)m * DIM + n0 + nl)       = pack_h(v0x, v0y);
                *(uint32_t*)(ob + (size_t)(m + 8) * DIM + n0 + nl) = pack_h(v1x, v1y);
            } else {
                const int n = n0 + nl;
                const size_t rb = (size_t)((m >> 10) * 768);
                const int s = m & (SEQ - 1);
                ovt[(rb + n)     * SEQ + s]     = __float2half(v0x);
                ovt[(rb + n + 1) * SEQ + s]     = __float2half(v0y);
                ovt[(rb + n)     * SEQ + s + 8] = __float2half(v1x);
                ovt[(rb + n + 1) * SEQ + s + 8] = __float2half(v1y);
            }
        }
    }
}

__global__ __launch_bounds__(256, 2) void fold_gemm_kernel(
    const __half* __restrict__ wk, const __half* __restrict__ wv,
    const __half* __restrict__ woT, const float* __restrict__ zero,
    __half* __restrict__ wkv)
{
    extern __shared__ __align__(128) float smf[];
    float* sBias = smf;
    uint32_t* sT = (uint32_t*)(smf + 128);

    const int tid = threadIdx.x;
    const int n0 = blockIdx.x * 128;
    const int m0 = blockIdx.y * 128;
    const int z  = blockIdx.z;
    const int li = (z < 2) ? 1 : 2;

    const __half* A = ((z & 1) == 0 ? wk : wv) + (size_t)li * D2;
    const __half* W = woT + (size_t)(li - 1) * D2;
    __half* O = wkv + (size_t)z * D2;

    GemmAcc Ac;
    gemm_mainloop(A, W, zero, sBias, sT, m0, n0, tid, Ac);

    const int lane = tid & 31, wid = tid >> 5;
    const int g = lane >> 2, t = lane & 3;
    const int wm = wid & 3, wn = wid >> 2;

    #pragma unroll
    for (int mt = 0; mt < 2; mt++) {
        const int m = m0 + wm * 32 + mt * 16 + g;
        #pragma unroll
        for (int nt = 0; nt < 8; nt++) {
            const int nl = wn * 64 + nt * 8 + 2 * t;
            *(uint32_t*)(O + (size_t)m * DIM + n0 + nl) =
                pack_h(Ac.a[mt][nt][0], Ac.a[mt][nt][1]);
            *(uint32_t*)(O + (size_t)(m + 8) * DIM + n0 + nl) =
                pack_h(Ac.a[mt][nt][2], Ac.a[mt][nt][3]);
        }
    }
}

__global__ __launch_bounds__(256, 2) void gemm_ofin_kernel(
    const __half* __restrict__ X, const __half* __restrict__ W,
    const float* __restrict__ bias, const float* __restrict__ add,
    float* __restrict__ out)
{
    extern __shared__ __align__(128) float smf[];
    float* sBias = smf;
    uint32_t* sT = (uint32_t*)(smf + 128);

    const int tid = threadIdx.x;
    const int n0 = blockIdx.x * 128;
    const int m0 = blockIdx.y * 128;

    GemmAcc A;
    gemm_mainloop(X, W, bias, sBias, sT, m0, n0, tid, A);

    const int lane = tid & 31, wid = tid >> 5;
    const int g = lane >> 2, t = lane & 3;
    const int wm = wid & 3, wn = wid >> 2;

    #pragma unroll
    for (int mt = 0; mt < 2; mt++) {
        const int m = m0 + wm * 32 + mt * 16 + g;
        #pragma unroll
        for (int nt = 0; nt < 8; nt++) {
            const int nl = wn * 64 + nt * 8 + 2 * t;
            const size_t o0 = (size_t)m * DIM + n0 + nl;
            const size_t o1 = (size_t)(m + 8) * DIM + n0 + nl;
            float2 a0 = *reinterpret_cast<const float2*>(add + o0);
            float2 a1 = *reinterpret_cast<const float2*>(add + o1);
            *reinterpret_cast<float2*>(out + o0) =
                make_float2(A.a[mt][nt][0] + sBias[nl] + a0.x,
                            A.a[mt][nt][1] + sBias[nl + 1] + a0.y);
            *reinterpret_cast<float2*>(out + o1) =
                make_float2(A.a[mt][nt][2] + sBias[nl] + a1.x,
                            A.a[mt][nt][3] + sBias[nl + 1] + a1.y);
        }
    }
}

// ---------------- fp16 flash attention (smem mask pipeline) ----------------
// SMEM layout (words): [0, 3*KV_SLOTW) KV stages | [MOFFW, +3*MSK_SLOTW) mask
// stages (stage 2 doubles as Q staging: same size & row stride).
#define APW 36
#define KV_SLOTW (64*APW*2)          // 4608 words
#define MSK_SLOTW (128*APW/2*2)      // 128 rows x 36 words = 4608 words
#define ASTG 3
#define MOFFW (ASTG*KV_SLOTW)        // 13824
#define ATTN_SMEM ((MOFFW + 3*4608) * 4)   // 110592 B

__global__ __launch_bounds__(256, 2) void attn_h_kernel(
    const __half* __restrict__ q, const __half* __restrict__ k,
    const __half* __restrict__ vt, const __half* __restrict__ distm,
    __half* __restrict__ ctx)
{
    extern __shared__ __align__(128) uint32_t smw[];
    const uint32_t base = smem_u32(smw);

    const int tid  = threadIdx.x;
    const int lane = tid & 31, wid = tid >> 5;
    const int g = lane >> 2, t = lane & 3;
    const int j  = lane >> 3, r7 = lane & 7;
    const int bRow = (j >> 1) * 8 + r7, bCol = (j & 1) * 4;

    const int b = blockIdx.z, h = blockIdx.y;
    const int q0 = blockIdx.x * 128;

    const __half* qb = q + (size_t)b * SEQ * DIM + h * DKH;
    const __half* kb = k + (size_t)b * SEQ * DIM + h * DKH;
    const __half* vb = vt + ((size_t)b * 768 + h * DKH) * SEQ;
    const __half* dm = distm + (size_t)b * SEQ * SEQ + (size_t)q0 * SEQ;

    const int qi0 = q0 + wid * 16 + g;
    const int qi1 = qi0 + 8;

    // KV + mask loader: one commit group per tile
    auto load_kvm = [&](int kt) {
        const int slot = kt % ASTG;
        const uint32_t dst  = base + (uint32_t)slot * (KV_SLOTW * 4);
        const uint32_t mdst = base + (uint32_t)(MOFFW + slot * 4608) * 4;
        const __half* gk = kb + (size_t)kt * 64 * DIM;
        const __half* gv = vb + kt * 64;
        const __half* gm = dm + kt * 64;
        #pragma unroll
        for (int i = 0; i < 2; i++) {
            int idx = tid + i * 256;
            int row = idx >> 3, f = idx & 7;
            CP_ASYNC16(dst + (uint32_t)(row * APW + f * 4) * 4,
                       gk + (size_t)row * DIM + f * 8);
            CP_ASYNC16(dst + (uint32_t)(64 * APW + row * APW + f * 4) * 4,
                       gv + (size_t)row * SEQ + f * 8);
        }
        #pragma unroll
        for (int i = 0; i < 4; i++) {
            int idx = tid + i * 256;        // 0..1023
            int row = idx >> 3, f = idx & 7;  // row 0..127
            CP_ASYNC16(mdst + (uint32_t)(row * APW + f * 4) * 4,
                       gm + (size_t)row * SEQ + f * 8);
        }
        CP_COMMIT();
    };

    // prologue: Q into mask-slot-2 region, overlapped with kvm0/kvm1
    {
        const uint32_t qdst = base + (uint32_t)(MOFFW + 2 * 4608) * 4;
        #pragma unroll
        for (int i = 0; i < 4; i++) {
            int idx = tid + i * 256;
            int row = idx >> 3, f = idx & 7;
            CP_ASYNC16(qdst + (uint32_t)(row * APW + f * 4) * 4,
                       qb + (size_t)(q0 + row) * DIM + f * 8);
        }
        CP_COMMIT();
    }
    load_kvm(0);
    load_kvm(1);
    cp_wait<2>();           // Q retired; kvm0/kvm1 still in flight
    __syncthreads();

    uint32_t qf[4][4];
    {
        const uint32_t* qp0 = smw + MOFFW + 2 * 4608 + (wid * 16 + g) * APW;
        const uint32_t* qp1 = qp0 + 8 * APW;
        #pragma unroll
        for (int ks = 0; ks < 4; ks++) {
            qf[ks][0] = qp0[ks * 8 + t];
            qf[ks][1] = qp1[ks * 8 + t];
            qf[ks][2] = qp0[ks * 8 + t + 4];
            qf[ks][3] = qp1[ks * 8 + t + 4];
        }
    }

    float Of[8][4];
    #pragma unroll
    for (int nt = 0; nt < 8; nt++)
        #pragma unroll
        for (int i = 0; i < 4; i++) Of[nt][i] = 0.f;
    float m_run0 = -1e30f, m_run1 = -1e30f, z_run0 = 0.f, z_run1 = 0.f;

    for (int kt = 0; kt < 16; kt++) {
        if (kt < 15) cp_wait<1>(); else cp_wait<0>();
        __syncthreads();   // also: all warps done reading Q region before m2 load
        if (kt + 2 < 16) load_kvm(kt + 2);

        const int slot = kt % ASTG;
        const uint32_t ksAddr = base + (uint32_t)slot * (KV_SLOTW * 4);
        const uint32_t vsAddr = ksAddr + 64 * APW * 4;
        const uint32_t* mp0 = smw + MOFFW + slot * 4608 + (wid * 16 + g) * APW;
        const uint32_t* mp1 = mp0 + 8 * APW;
        const int kbase = kt * 64;

        // ---- S = Q K^T ----
        float Sf[8][4];
        #pragma unroll
        for (int nt = 0; nt < 8; nt++)
            #pragma unroll
            for (int i = 0; i < 4; i++) Sf[nt][i] = 0.f;
        #pragma unroll
        for (int ks = 0; ks < 4; ks++) {
            uint32_t kf[8][2];
            #pragma unroll
            for (int p = 0; p < 4; p++) {
                uint32_t rr[4];
                ldsm4(rr, ksAddr + (uint32_t)((p * 16 + bRow) * APW
                                              + ks * 8 + bCol) * 4);
                kf[2*p][0]   = rr[0]; kf[2*p][1]   = rr[1];
                kf[2*p+1][0] = rr[2]; kf[2*p+1][1] = rr[3];
            }
            #pragma unroll
            for (int nt = 0; nt < 8; nt++)
                mma16(Sf[nt], qf[ks], kf[nt]);
        }

        // ---- online softmax ----
        float mloc0 = -1e30f, mloc1 = -1e30f;
        #pragma unroll
        for (int nt = 0; nt < 8; nt++) {
            mloc0 = fmaxf(mloc0, fmaxf(Sf[nt][0], Sf[nt][1]));
            mloc1 = fmaxf(mloc1, fmaxf(Sf[nt][2], Sf[nt][3]));
        }
        #pragma unroll
        for (int off = 1; off <= 2; off <<= 1) {
            mloc0 = fmaxf(mloc0, __shfl_xor_sync(0xffffffffu, mloc0, off));
            mloc1 = fmaxf(mloc1, __shfl_xor_sync(0xffffffffu, mloc1, off));
        }
        const float mnew0 = fmaxf(m_run0, mloc0);
        const float mnew1 = fmaxf(m_run1, mloc1);
        const float f0 = exp2f(m_run0 - mnew0);
        const float f1 = exp2f(m_run1 - mnew1);
        z_run0 *= f0; z_run1 *= f1;
        #pragma unroll
        for (int nt = 0; nt < 8; nt++) {
            Of[nt][0] *= f0; Of[nt][1] *= f0;
            Of[nt][2] *= f1; Of[nt][3] *= f1;
        }

        // ---- exp + mask (from smem) -> P in registers ----
        float zs0 = 0.f, zs1 = 0.f;
        uint32_t Pr0[8], Pr1[8];
        #pragma unroll
        for (int h2 = 0; h2 < 2; h2++) {
            float2 md0[4], md1[4];
            #pragma unroll
            for (int jj = 0; jj < 4; jj++) {
                const int nt = h2 * 4 + jj;
                const int ki = kbase + nt * 8 + 2 * t;
                md0[jj] = __half22float2(
                    *reinterpret_cast<const __half2*>(mp0 + nt * 4 + t));
                md1[jj] = __half22float2(
                    *reinterpret_cast<const __half2*>(mp1 + nt * 4 + t));
                if (qi0 == ki)     md0[jj].x += 1.f;
                if (qi0 == ki + 1) md0[jj].y += 1.f;
                if (qi1 == ki)     md1[jj].x += 1.f;
                if (qi1 == ki + 1) md1[jj].y += 1.f;
            }
            #pragma unroll
            for (int jj = 0; jj < 4; jj++) {
                const int nt = h2 * 4 + jj;
                float2 e01 = exp2_pair(Sf[nt][0] - mnew0, Sf[nt][1] - mnew0);
                float2 e23 = exp2_pair(Sf[nt][2] - mnew1, Sf[nt][3] - mnew1);
                zs0 += e01.x + e01.y;
                zs1 += e23.x + e23.y;
                Pr0[nt] = pack_h(e01.x * md0[jj].x, e01.y * md0[jj].y);
                Pr1[nt] = pack_h(e23.x * md1[jj].x, e23.y * md1[jj].y);
            }
        }
        #pragma unroll
        for (int off = 1; off <= 2; off <<= 1) {
            zs0 += __shfl_xor_sync(0xffffffffu, zs0, off);
            zs1 += __shfl_xor_sync(0xffffffffu, zs1, off);
        }
        z_run0 += zs0; z_run1 += zs1;
        m_run0 = mnew0; m_run1 = mnew1;

        // ---- O += P V directly from registers ----
        #pragma unroll
        for (int ks = 0; ks < 4; ks++) {
            uint32_t af[4] = { Pr0[2*ks], Pr1[2*ks], Pr0[2*ks+1], Pr1[2*ks+1] };
            uint32_t vf[8][2];
            #pragma unroll
            for (int p = 0; p < 4; p++) {
                uint32_t rr[4];
                ldsm4(rr, vsAddr + (uint32_t)((p * 16 + bRow) * APW
                                              + ks * 8 + bCol) * 4);
                vf[2*p][0]   = rr[0]; vf[2*p][1]   = rr[1];
                vf[2*p+1][0] = rr[2]; vf[2*p+1][1] = rr[3];
            }
            #pragma unroll
            for (int nt = 0; nt < 8; nt++)
                mma16(Of[nt], af, vf[nt]);
        }
    }

    const float inv0 = 1.f / z_run0, inv1 = 1.f / z_run1;
    #pragma unroll
    for (int nt = 0; nt < 8; nt++) {
        const int d = h * DKH + nt * 8 + 2 * t;
        *(uint32_t*)(ctx + ((size_t)b * SEQ + qi0) * DIM + d) =
            pack_h(Of[nt][0] * inv0, Of[nt][1] * inv0);
        *(uint32_t*)(ctx + ((size_t)b * SEQ + qi1) * DIM + d) =
            pack_h(Of[nt][2] * inv1, Of[nt][3] * inv1);
    }
}

// ---------------- host ----------------
extern "C" void kernel_launch(void* const* d_in, const int* in_sizes, int n_in,
                              void* d_out, int out_size)
{
    const float* Q    = (const float*)d_in[0];
    const float* Kin  = (const float*)d_in[1];
    const float* Vin  = (const float*)d_in[2];
    const float* dist = (const float*)d_in[3];
    const float* Wq   = (const float*)d_in[4];
    const float* bq   = (const float*)d_in[5];
    const float* Wk   = (const float*)d_in[6];
    const float* bk   = (const float*)d_in[7];
    const float* Wv   = (const float*)d_in[8];
    const float* bv   = (const float*)d_in[9];
    const float* Wo   = (const float*)d_in[10];
    const float* bo   = (const float*)d_in[11];
    float* out = (float*)d_out;

    __half *qin, *kin, *vin, *qh, *kh, *vtb, *ctxb, *dmh;
    __half *wqh, *wkh, *wvh, *woh, *woT, *wkv;
    float *bkv, *zero;
    cudaGetSymbolAddress((void**)&qin,  g_qin);
    cudaGetSymbolAddress((void**)&kin,  g_kin);
    cudaGetSymbolAddress((void**)&vin,  g_vin);
    cudaGetSymbolAddress((void**)&qh,   g_qh);
    cudaGetSymbolAddress((void**)&kh,   g_kh);
    cudaGetSymbolAddress((void**)&vtb,  g_vt);
    cudaGetSymbolAddress((void**)&ctxb, g_ctx);
    cudaGetSymbolAddress((void**)&dmh,  g_dmh);
    cudaGetSymbolAddress((void**)&wqh,  g_wq);
    cudaGetSymbolAddress((void**)&wkh,  g_wk);
    cudaGetSymbolAddress((void**)&wvh,  g_wv);
    cudaGetSymbolAddress((void**)&woh,  g_wo);
    cudaGetSymbolAddress((void**)&woT,  g_woT);
    cudaGetSymbolAddress((void**)&wkv,  g_wkv);
    cudaGetSymbolAddress((void**)&bkv,  g_bkv);
    cudaGetSymbolAddress((void**)&zero, g_zero);

    cudaFuncSetAttribute(gemm_qkv_kernel,
                         cudaFuncAttributeMaxDynamicSharedMemorySize, GEMM_SMEM);
    cudaFuncSetAttribute(fold_gemm_kernel,
                         cudaFuncAttributeMaxDynamicSharedMemorySize, GEMM_SMEM);
    cudaFuncSetAttribute(gemm_ofin_kernel,
                         cudaFuncAttributeMaxDynamicSharedMemorySize, GEMM_SMEM);
    cudaFuncSetAttribute(attn_h_kernel,
                         cudaFuncAttributeMaxDynamicSharedMemorySize, ATTN_SMEM);

    {
        const int nAct4 = MTOT * DIM / 4;
        const int nW4   = NL * D2 / 4;
        const int nD4   = BSZ * SEQ * SEQ / 4;
        dim3 ga((nAct4 + 255) / 256, 3);
        f2h_acts_kernel<<<ga, 256>>>((const float4*)Q, (const float4*)Kin,
                                     (const float4*)Vin,
                                     (uint2*)qin, (uint2*)kin, (uint2*)vin, nAct4);
        dim3 gw((nW4 + 255) / 256, 4);
        f2h_w_kernel<<<gw, 256>>>((const float4*)Wq, (const float4*)Wk,
                                  (const float4*)Wv, (const float4*)Wo,
                                  (uint2*)wqh, (uint2*)wkh, (uint2*)wvh, (uint2*)woh, nW4);
        f2h_dist_kernel<<<(nD4 + 255) / 256, 256>>>((const float4*)dist,
                                                    (uint2*)dmh, nD4);
        dim3 gt(24, 24, 2);
        transpose_w_kernel<<<gt, dim3(32, 8)>>>(woh, woT);
        dim3 gf(6, 6, 4);
        fold_gemm_kernel<<<gf, 256, GEMM_SMEM>>>(wkh, wvh, woT, zero, wkv);
        dim3 gb(6, 4);
        biasfold_kernel<<<gb, 128>>>(Wk, Wv, bk, bv, bo, bkv);
    }

    const float qscale = 0.125f * 1.4426950408889634f;  // log2(e)/sqrt(64)
    dim3 qkvgrid(18, MTOT / 128);
    dim3 ogrid(DIM / 128, MTOT / 128);
    dim3 agrid(SEQ / 128, NH, BSZ);

    // layer 1
    gemm_qkv_kernel<<<qkvgrid, 256, GEMM_SMEM>>>(
        qin, kin, vin, wqh, wkh, wvh, bq, bk, bv, qh, kh, vtb, qscale);
    attn_h_kernel<<<agrid, 256, ATTN_SMEM>>>(qh, kh, vtb, dmh, ctxb);
    // layer 2 (folded K/V from ctx)
    gemm_qkv_kernel<<<qkvgrid, 256, GEMM_SMEM>>>(
        qin, ctxb, ctxb, wqh + D2, wkv, wkv + D2,
        bq + DIM, bkv, bkv + DIM, qh, kh, vtb, qscale);
    attn_h_kernel<<<agrid, 256, ATTN_SMEM>>>(qh, kh, vtb, dmh, ctxb);
    // layer 3 (folded)
    gemm_qkv_kernel<<<qkvgrid, 256, GEMM_SMEM>>>(
        qin, ctxb, ctxb, wqh + 2 * (size_t)D2, wkv + 2 * (size_t)D2, wkv + 3 * (size_t)D2,
        bq + 2 * DIM, bkv + 2 * DIM, bkv + 3 * DIM, qh, kh, vtb, qscale);
    attn_h_kernel<<<agrid, 256, ATTN_SMEM>>>(qh, kh, vtb, dmh, ctxb);
    // final
    gemm_ofin_kernel<<<ogrid, 256, GEMM_SMEM>>>(ctxb, woh + 2 * (size_t)D2,
                                                bo + 2 * DIM, Vin, out);
}

// round 17
// speedup vs baseline: 1.2085x; 1.0505x over previous
#include <cuda_runtime.h>
#include <cuda_fp16.h>
#include <cstdint>
#include <math.h>

#define BSZ 8
#define SEQ 1024
#define DIM 768
#define NH  12
#define DKH 64
#define NL  3
#define MTOT (BSZ*SEQ)
#define D2   (DIM*DIM)

__device__ __half g_qin [MTOT*DIM];
__device__ __half g_kin [MTOT*DIM];
__device__ __half g_vin [MTOT*DIM];
__device__ __half g_qh  [MTOT*DIM];
__device__ __half g_kh  [MTOT*DIM];
__device__ __half g_vt  [MTOT*DIM];   // V transposed per (b): [(b*768+d)][SEQ]
__device__ __half g_ctx [MTOT*DIM];
__device__ __half g_wq  [NL*D2];
__device__ __half g_wk  [NL*D2];
__device__ __half g_wv  [NL*D2];
__device__ __half g_wo  [NL*D2];
__device__ __half g_woT [2*D2];       // Wo^T of layers 0,1
__device__ __half g_wkv [4*D2];       // folded Wk1Wo0, Wv1Wo0, Wk2Wo1, Wv2Wo1
__device__ float  g_bkv [4*DIM];
__device__ float  g_zero[DIM];        // zero-initialized
__device__ __half g_dmh [BSZ*SEQ*SEQ]; // dist in fp16 (mask; diag added in-kernel)

__device__ __forceinline__ uint32_t smem_u32(const void* p) {
    uint32_t a;
    asm("{ .reg .u64 t; cvta.to.shared.u64 t, %1; cvt.u32.u64 %0, t; }"
        : "=r"(a) : "l"(p));
    return a;
}
// pack two fp32 -> fp16x2 (lo = first arg in memory order)
__device__ __forceinline__ uint32_t pack_h(float lo, float hi) {
    uint32_t r;
    asm("cvt.rn.f16x2.f32 %0, %1, %2;" : "=r"(r) : "f"(hi), "f"(lo));
    return r;
}
__device__ __forceinline__ void mma16(float* d, const uint32_t* a, const uint32_t* b) {
    asm volatile(
        "mma.sync.aligned.m16n8k16.row.col.f32.f16.f16.f32 "
        "{%0,%1,%2,%3}, {%4,%5,%6,%7}, {%8,%9}, {%0,%1,%2,%3};"
        : "+f"(d[0]), "+f"(d[1]), "+f"(d[2]), "+f"(d[3])
        : "r"(a[0]), "r"(a[1]), "r"(a[2]), "r"(a[3]), "r"(b[0]), "r"(b[1]));
}
__device__ __forceinline__ void ldsm4(uint32_t* r, uint32_t addr) {
    asm volatile("ldmatrix.sync.aligned.m8n8.x4.shared.b16 {%0,%1,%2,%3}, [%4];"
        : "=r"(r[0]), "=r"(r[1]), "=r"(r[2]), "=r"(r[3]) : "r"(addr));
}
// paired exp2 in fp16 (1 MUFU op for 2 scores), returns fp32 pair
__device__ __forceinline__ float2 exp2_pair(float s0, float s1) {
    uint32_t h;
    asm("cvt.rn.f16x2.f32 %0, %1, %2;" : "=r"(h) : "f"(s1), "f"(s0));
    asm("ex2.approx.f16x2 %0, %0;" : "+r"(h));
    __half2 e = *reinterpret_cast<__half2*>(&h);
    return __half22float2(e);
}
#define CP_ASYNC16(s, g) \
    asm volatile("cp.async.cg.shared.global [%0], [%1], 16;" \
                 :: "r"(s), "l"(g) : "memory")
#define CP_COMMIT() asm volatile("cp.async.commit_group;" ::: "memory")
template<int N> __device__ __forceinline__ void cp_wait() {
    asm volatile("cp.async.wait_group %0;" :: "n"(N) : "memory");
}

// ---------------- converters / prep ----------------
__global__ void f2h_acts_kernel(
    const float4* __restrict__ a0, const float4* __restrict__ a1,
    const float4* __restrict__ a2,
    uint2* __restrict__ o0, uint2* __restrict__ o1, uint2* __restrict__ o2, int n4)
{
    int i = blockIdx.x * blockDim.x + threadIdx.x;
    if (i >= n4) return;
    const float4* in = blockIdx.y == 0 ? a0 : blockIdx.y == 1 ? a1 : a2;
    uint2* out       = blockIdx.y == 0 ? o0 : blockIdx.y == 1 ? o1 : o2;
    float4 f = in[i];
    out[i] = make_uint2(pack_h(f.x, f.y), pack_h(f.z, f.w));
}
__global__ void f2h_w_kernel(
    const float4* __restrict__ a0, const float4* __restrict__ a1,
    const float4* __restrict__ a2, const float4* __restrict__ a3,
    uint2* __restrict__ o0, uint2* __restrict__ o1,
    uint2* __restrict__ o2, uint2* __restrict__ o3, int n4)
{
    int i = blockIdx.x * blockDim.x + threadIdx.x;
    if (i >= n4) return;
    const float4* in = blockIdx.y == 0 ? a0 : blockIdx.y == 1 ? a1
                     : blockIdx.y == 2 ? a2 : a3;
    uint2* out       = blockIdx.y == 0 ? o0 : blockIdx.y == 1 ? o1
                     : blockIdx.y == 2 ? o2 : o3;
    float4 f = in[i];
    out[i] = make_uint2(pack_h(f.x, f.y), pack_h(f.z, f.w));
}
__global__ void f2h_dist_kernel(const float4* __restrict__ in,
                                uint2* __restrict__ out, int n4)
{
    int i = blockIdx.x * blockDim.x + threadIdx.x;
    if (i >= n4) return;
    float4 f = in[i];
    out[i] = make_uint2(pack_h(f.x, f.y), pack_h(f.z, f.w));
}
__global__ void transpose_w_kernel(const __half* __restrict__ src,
                                   __half* __restrict__ dst)
{
    __shared__ __half tile[32][33];
    const int l = blockIdx.z;
    const __half* s = src + (size_t)l * D2;
    __half* d = dst + (size_t)l * D2;
    const int x = blockIdx.x * 32 + threadIdx.x;
    const int y0 = blockIdx.y * 32;
    #pragma unroll
    for (int i = threadIdx.y; i < 32; i += 8)
        tile[i][threadIdx.x] = s[(size_t)(y0 + i) * DIM + x];
    __syncthreads();
    const int x2 = blockIdx.y * 32 + threadIdx.x;
    const int y2 = blockIdx.x * 32;
    #pragma unroll
    for (int i = threadIdx.y; i < 32; i += 8)
        d[(size_t)(y2 + i) * DIM + x2] = tile[threadIdx.x][i];
}
__global__ void biasfold_kernel(
    const float* __restrict__ Wk, const float* __restrict__ Wv,
    const float* __restrict__ bk, const float* __restrict__ bv,
    const float* __restrict__ bo, float* __restrict__ bkv)
{
    const int z = blockIdx.y;
    const int n = blockIdx.x * 128 + threadIdx.x;
    const int li = (z < 2) ? 1 : 2;
    const float* W  = ((z & 1) == 0 ? Wk : Wv) + (size_t)li * D2 + (size_t)n * DIM;
    const float* bs = ((z & 1) == 0 ? bk : bv) + li * DIM;
    const float* bsrc = bo + (li - 1) * DIM;
    float acc = 0.f;
    #pragma unroll 8
    for (int j = 0; j < DIM; j++) acc += W[j] * bsrc[j];
    bkv[z * DIM + n] = acc + bs[n];
}

// ---------------- GEMM core (fp16, ldmatrix, 3-stage, k-chunk 64) ----------------
#define GKW 36                         // words per 64-half row (stride proven CF)
#define GSLOTW (128*GKW)               // 4608 words per A or B tile
#define GSTG 3
#define GEMM_SMEM ((128 + GSTG*2*GSLOTW) * 4)   // 111104 B

struct GemmAcc { float a[2][8][4]; };

__device__ __forceinline__ void gemm_mainloop(
    const __half* __restrict__ X, const __half* __restrict__ W,
    const float* __restrict__ bias, float* sBias, uint32_t* sT,
    int m0, int n0, int tid, GemmAcc& A)
{
    const uint32_t tAddr = smem_u32(sT);
    const int lane = tid & 31, wid = tid >> 5;
    const int wm = wid & 3, wn = wid >> 2;
    const int j  = lane >> 3, r7 = lane & 7;
    const int aRow = (j & 1) * 8 + r7, aCol = (j >> 1) * 4;
    const int bRow = (j >> 1) * 8 + r7, bCol = (j & 1) * 4;

    if (tid < 128) sBias[tid] = bias[n0 + tid];

    #pragma unroll
    for (int mt = 0; mt < 2; mt++)
        #pragma unroll
        for (int nt = 0; nt < 8; nt++)
            #pragma unroll
            for (int i = 0; i < 4; i++) A.a[mt][nt][i] = 0.f;

    auto load_chunk = [&](int c) {
        const uint32_t base = tAddr + (uint32_t)(c % GSTG) * (2 * GSLOTW * 4);
        const __half* gA = X + (size_t)m0 * DIM + c * 64;
        const __half* gB = W + (size_t)n0 * DIM + c * 64;
        #pragma unroll
        for (int i = 0; i < 4; i++) {
            int idx = tid + i * 256;          // 0..1023
            int row = idx >> 3, f = idx & 7;  // 128 rows x 8x16B
            uint32_t d = base + (uint32_t)(row * GKW + f * 4) * 4;
            const size_t go = (size_t)row * DIM + f * 8;
            CP_ASYNC16(d, gA + go);
            CP_ASYNC16(d + GSLOTW * 4, gB + go);
        }
        CP_COMMIT();
    };

    load_chunk(0);
    load_chunk(1);
    for (int c = 0; c < 12; c++) {
        if (c < 11) cp_wait<1>(); else cp_wait<0>();
        __syncthreads();
        if (c + 2 < 12) load_chunk(c + 2);

        const uint32_t aB = tAddr + (uint32_t)(c % GSTG) * (2 * GSLOTW * 4);
        const uint32_t bB = aB + GSLOTW * 4;

        #pragma unroll
        for (int ks = 0; ks < 4; ks++) {
            uint32_t afr[2][4];
            #pragma unroll
            for (int mt = 0; mt < 2; mt++)
                ldsm4(afr[mt], aB + (uint32_t)((wm * 32 + mt * 16 + aRow) * GKW
                                               + ks * 8 + aCol) * 4);
            uint32_t bfr[8][2];
            #pragma unroll
            for (int p = 0; p < 4; p++) {
                uint32_t rr[4];
                ldsm4(rr, bB + (uint32_t)((wn * 64 + p * 16 + bRow) * GKW
                                          + ks * 8 + bCol) * 4);
                bfr[2*p][0]   = rr[0]; bfr[2*p][1]   = rr[1];
                bfr[2*p+1][0] = rr[2]; bfr[2*p+1][1] = rr[3];
            }
            #pragma unroll
            for (int nt = 0; nt < 8; nt++) {
                mma16(A.a[0][nt], afr[0], bfr[nt]);
                mma16(A.a[1][nt], afr[1], bfr[nt]);
            }
        }
    }
}

__global__ __launch_bounds__(256, 2) void gemm_qkv_kernel(
    const __half* __restrict__ xq, const __half* __restrict__ xk,
    const __half* __restrict__ xv,
    const __half* __restrict__ wq, const __half* __restrict__ wk,
    const __half* __restrict__ wv,
    const float* __restrict__ bq, const float* __restrict__ bk,
    const float* __restrict__ bv,
    __half* __restrict__ oq, __half* __restrict__ ok,
    __half* __restrict__ ovt, float qscale)
{
    extern __shared__ __align__(128) float smf[];
    float* sBias = smf;
    uint32_t* sT = (uint32_t*)(smf + 128);

    const int tid = threadIdx.x;
    const int slice = blockIdx.x / 6;
    const int n0 = (blockIdx.x % 6) * 128;
    const int m0 = blockIdx.y * 128;

    const __half* X = slice == 0 ? xq : slice == 1 ? xk : xv;
    const __half* W = slice == 0 ? wq : slice == 1 ? wk : wv;
    const float*  B = slice == 0 ? bq : slice == 1 ? bk : bv;

    GemmAcc A;
    gemm_mainloop(X, W, B, sBias, sT, m0, n0, tid, A);

    const int lane = tid & 31, wid = tid >> 5;
    const int g = lane >> 2, t = lane & 3;
    const int wm = wid & 3, wn = wid >> 2;
    const float scale = slice == 0 ? qscale : 1.0f;

    #pragma unroll
    for (int mt = 0; mt < 2; mt++) {
        const int m = m0 + wm * 32 + mt * 16 + g;
        #pragma unroll
        for (int nt = 0; nt < 8; nt++) {
            const int nl = wn * 64 + nt * 8 + 2 * t;
            float v0x = (A.a[mt][nt][0] + sBias[nl])     * scale;
            float v0y = (A.a[mt][nt][1] + sBias[nl + 1]) * scale;
            float v1x = (A.a[mt][nt][2] + sBias[nl])     * scale;
            float v1y = (A.a[mt][nt][3] + sBias[nl + 1]) * scale;
            if (slice < 2) {
                __half* ob = slice == 0 ? oq : ok;
                *(uint32_t*)(ob + (size_t)m * DIM + n0 + nl)       = pack_h(v0x, v0y);
                *(uint32_t*)(ob + (size_t)(m + 8) * DIM + n0 + nl) = pack_h(v1x, v1y);
            } else {
                const int n = n0 + nl;
                const size_t rb = (size_t)((m >> 10) * 768);
                const int s = m & (SEQ - 1);
                ovt[(rb + n)     * SEQ + s]     = __float2half(v0x);
                ovt[(rb + n + 1) * SEQ + s]     = __float2half(v0y);
                ovt[(rb + n)     * SEQ + s + 8] = __float2half(v1x);
                ovt[(rb + n + 1) * SEQ + s + 8] = __float2half(v1y);
            }
        }
    }
}

__global__ __launch_bounds__(256, 2) void fold_gemm_kernel(
    const __half* __restrict__ wk, const __half* __restrict__ wv,
    const __half* __restrict__ woT, const float* __restrict__ zero,
    __half* __restrict__ wkv)
{
    extern __shared__ __align__(128) float smf[];
    float* sBias = smf;
    uint32_t* sT = (uint32_t*)(smf + 128);

    const int tid = threadIdx.x;
    const int n0 = blockIdx.x * 128;
    const int m0 = blockIdx.y * 128;
    const int z  = blockIdx.z;
    const int li = (z < 2) ? 1 : 2;

    const __half* A = ((z & 1) == 0 ? wk : wv) + (size_t)li * D2;
    const __half* W = woT + (size_t)(li - 1) * D2;
    __half* O = wkv + (size_t)z * D2;

    GemmAcc Ac;
    gemm_mainloop(A, W, zero, sBias, sT, m0, n0, tid, Ac);

    const int lane = tid & 31, wid = tid >> 5;
    const int g = lane >> 2, t = lane & 3;
    const int wm = wid & 3, wn = wid >> 2;

    #pragma unroll
    for (int mt = 0; mt < 2; mt++) {
        const int m = m0 + wm * 32 + mt * 16 + g;
        #pragma unroll
        for (int nt = 0; nt < 8; nt++) {
            const int nl = wn * 64 + nt * 8 + 2 * t;
            *(uint32_t*)(O + (size_t)m * DIM + n0 + nl) =
                pack_h(Ac.a[mt][nt][0], Ac.a[mt][nt][1]);
            *(uint32_t*)(O + (size_t)(m + 8) * DIM + n0 + nl) =
                pack_h(Ac.a[mt][nt][2], Ac.a[mt][nt][3]);
        }
    }
}

__global__ __launch_bounds__(256, 2) void gemm_ofin_kernel(
    const __half* __restrict__ X, const __half* __restrict__ W,
    const float* __restrict__ bias, const float* __restrict__ add,
    float* __restrict__ out)
{
    extern __shared__ __align__(128) float smf[];
    float* sBias = smf;
    uint32_t* sT = (uint32_t*)(smf + 128);

    const int tid = threadIdx.x;
    const int n0 = blockIdx.x * 128;
    const int m0 = blockIdx.y * 128;

    GemmAcc A;
    gemm_mainloop(X, W, bias, sBias, sT, m0, n0, tid, A);

    const int lane = tid & 31, wid = tid >> 5;
    const int g = lane >> 2, t = lane & 3;
    const int wm = wid & 3, wn = wid >> 2;

    #pragma unroll
    for (int mt = 0; mt < 2; mt++) {
        const int m = m0 + wm * 32 + mt * 16 + g;
        #pragma unroll
        for (int nt = 0; nt < 8; nt++) {
            const int nl = wn * 64 + nt * 8 + 2 * t;
            const size_t o0 = (size_t)m * DIM + n0 + nl;
            const size_t o1 = (size_t)(m + 8) * DIM + n0 + nl;
            float2 a0 = *reinterpret_cast<const float2*>(add + o0);
            float2 a1 = *reinterpret_cast<const float2*>(add + o1);
            *reinterpret_cast<float2*>(out + o0) =
                make_float2(A.a[mt][nt][0] + sBias[nl] + a0.x,
                            A.a[mt][nt][1] + sBias[nl + 1] + a0.y);
            *reinterpret_cast<float2*>(out + o1) =
                make_float2(A.a[mt][nt][2] + sBias[nl] + a1.x,
                            A.a[mt][nt][3] + sBias[nl + 1] + a1.y);
        }
    }
}

// ---------------- fp16 flash attention (smem mask pipeline) ----------------
#define APW 36
#define KV_SLOTW (64*APW*2)          // 4608 words
#define ASTG 3
#define MOFFW (ASTG*KV_SLOTW)        // 13824
#define ATTN_SMEM ((MOFFW + 3*4608) * 4)   // 110592 B

__global__ __launch_bounds__(256, 2) void attn_h_kernel(
    const __half* __restrict__ q, const __half* __restrict__ k,
    const __half* __restrict__ vt, const __half* __restrict__ distm,
    __half* __restrict__ ctx)
{
    extern __shared__ __align__(128) uint32_t smw[];
    const uint32_t base = smem_u32(smw);

    const int tid  = threadIdx.x;
    const int lane = tid & 31, wid = tid >> 5;
    const int g = lane >> 2, t = lane & 3;
    const int j  = lane >> 3, r7 = lane & 7;
    const int bRow = (j >> 1) * 8 + r7, bCol = (j & 1) * 4;

    const int b = blockIdx.z, h = blockIdx.y;
    const int q0 = blockIdx.x * 128;

    const __half* qb = q + (size_t)b * SEQ * DIM + h * DKH;
    const __half* kb = k + (size_t)b * SEQ * DIM + h * DKH;
    const __half* vb = vt + ((size_t)b * 768 + h * DKH) * SEQ;
    const __half* dm = distm + (size_t)b * SEQ * SEQ + (size_t)q0 * SEQ;

    const int qi0 = q0 + wid * 16 + g;
    const int qi1 = qi0 + 8;

    auto load_kvm = [&](int kt) {
        const int slot = kt % ASTG;
        const uint32_t dst  = base + (uint32_t)slot * (KV_SLOTW * 4);
        const uint32_t mdst = base + (uint32_t)(MOFFW + slot * 4608) * 4;
        const __half* gk = kb + (size_t)kt * 64 * DIM;
        const __half* gv = vb + kt * 64;
        const __half* gm = dm + kt * 64;
        #pragma unroll
        for (int i = 0; i < 2; i++) {
            int idx = tid + i * 256;
            int row = idx >> 3, f = idx & 7;
            CP_ASYNC16(dst + (uint32_t)(row * APW + f * 4) * 4,
                       gk + (size_t)row * DIM + f * 8);
            CP_ASYNC16(dst + (uint32_t)(64 * APW + row * APW + f * 4) * 4,
                       gv + (size_t)row * SEQ + f * 8);
        }
        #pragma unroll
        for (int i = 0; i < 4; i++) {
            int idx = tid + i * 256;
            int row = idx >> 3, f = idx & 7;
            CP_ASYNC16(mdst + (uint32_t)(row * APW + f * 4) * 4,
                       gm + (size_t)row * SEQ + f * 8);
        }
        CP_COMMIT();
    };

    // prologue: Q into mask-slot-2 region, overlapped with kvm0/kvm1
    {
        const uint32_t qdst = base + (uint32_t)(MOFFW + 2 * 4608) * 4;
        #pragma unroll
        for (int i = 0; i < 4; i++) {
            int idx = tid + i * 256;
            int row = idx >> 3, f = idx & 7;
            CP_ASYNC16(qdst + (uint32_t)(row * APW + f * 4) * 4,
                       qb + (size_t)(q0 + row) * DIM + f * 8);
        }
        CP_COMMIT();
    }
    load_kvm(0);
    load_kvm(1);
    cp_wait<2>();
    __syncthreads();

    uint32_t qf[4][4];
    {
        const uint32_t* qp0 = smw + MOFFW + 2 * 4608 + (wid * 16 + g) * APW;
        const uint32_t* qp1 = qp0 + 8 * APW;
        #pragma unroll
        for (int ks = 0; ks < 4; ks++) {
            qf[ks][0] = qp0[ks * 8 + t];
            qf[ks][1] = qp1[ks * 8 + t];
            qf[ks][2] = qp0[ks * 8 + t + 4];
            qf[ks][3] = qp1[ks * 8 + t + 4];
        }
    }

    float Of[8][4];
    #pragma unroll
    for (int nt = 0; nt < 8; nt++)
        #pragma unroll
        for (int i = 0; i < 4; i++) Of[nt][i] = 0.f;
    float m_run0 = -1e30f, m_run1 = -1e30f, z_run0 = 0.f, z_run1 = 0.f;

    for (int kt = 0; kt < 16; kt++) {
        if (kt < 15) cp_wait<1>(); else cp_wait<0>();
        __syncthreads();
        if (kt + 2 < 16) load_kvm(kt + 2);

        const int slot = kt % ASTG;
        const uint32_t ksAddr = base + (uint32_t)slot * (KV_SLOTW * 4);
        const uint32_t vsAddr = ksAddr + 64 * APW * 4;
        const uint32_t* mp0 = smw + MOFFW + slot * 4608 + (wid * 16 + g) * APW;
        const uint32_t* mp1 = mp0 + 8 * APW;
        const int kbase = kt * 64;

        float Sf[8][4];
        #pragma unroll
        for (int nt = 0; nt < 8; nt++)
            #pragma unroll
            for (int i = 0; i < 4; i++) Sf[nt][i] = 0.f;
        #pragma unroll
        for (int ks = 0; ks < 4; ks++) {
            uint32_t kf[8][2];
            #pragma unroll
            for (int p = 0; p < 4; p++) {
                uint32_t rr[4];
                ldsm4(rr, ksAddr + (uint32_t)((p * 16 + bRow) * APW
                                              + ks * 8 + bCol) * 4);
                kf[2*p][0]   = rr[0]; kf[2*p][1]   = rr[1];
                kf[2*p+1][0] = rr[2]; kf[2*p+1][1] = rr[3];
            }
            #pragma unroll
            for (int nt = 0; nt < 8; nt++)
                mma16(Sf[nt], qf[ks], kf[nt]);
        }

        float mloc0 = -1e30f, mloc1 = -1e30f;
        #pragma unroll
        for (int nt = 0; nt < 8; nt++) {
            mloc0 = fmaxf(mloc0, fmaxf(Sf[nt][0], Sf[nt][1]));
            mloc1 = fmaxf(mloc1, fmaxf(Sf[nt][2], Sf[nt][3]));
        }
        #pragma unroll
        for (int off = 1; off <= 2; off <<= 1) {
            mloc0 = fmaxf(mloc0, __shfl_xor_sync(0xffffffffu, mloc0, off));
            mloc1 = fmaxf(mloc1, __shfl_xor_sync(0xffffffffu, mloc1, off));
        }
        const float mnew0 = fmaxf(m_run0, mloc0);
        const float mnew1 = fmaxf(m_run1, mloc1);
        const float f0 = exp2f(m_run0 - mnew0);
        const float f1 = exp2f(m_run1 - mnew1);
        z_run0 *= f0; z_run1 *= f1;
        #pragma unroll
        for (int nt = 0; nt < 8; nt++) {
            Of[nt][0] *= f0; Of[nt][1] *= f0;
            Of[nt][2] *= f1; Of[nt][3] *= f1;
        }

        float zs0 = 0.f, zs1 = 0.f;
        uint32_t Pr0[8], Pr1[8];
        #pragma unroll
        for (int h2 = 0; h2 < 2; h2++) {
            float2 md0[4], md1[4];
            #pragma unroll
            for (int jj = 0; jj < 4; jj++) {
                const int nt = h2 * 4 + jj;
                const int ki = kbase + nt * 8 + 2 * t;
                md0[jj] = __half22float2(
                    *reinterpret_cast<const __half2*>(mp0 + nt * 4 + t));
                md1[jj] = __half22float2(
                    *reinterpret_cast<const __half2*>(mp1 + nt * 4 + t));
                if (qi0 == ki)     md0[jj].x += 1.f;
                if (qi0 == ki + 1) md0[jj].y += 1.f;
                if (qi1 == ki)     md1[jj].x += 1.f;
                if (qi1 == ki + 1) md1[jj].y += 1.f;
            }
            #pragma unroll
            for (int jj = 0; jj < 4; jj++) {
                const int nt = h2 * 4 + jj;
                float2 e01 = exp2_pair(Sf[nt][0] - mnew0, Sf[nt][1] - mnew0);
                float2 e23 = exp2_pair(Sf[nt][2] - mnew1, Sf[nt][3] - mnew1);
                zs0 += e01.x + e01.y;
                zs1 += e23.x + e23.y;
                Pr0[nt] = pack_h(e01.x * md0[jj].x, e01.y * md0[jj].y);
                Pr1[nt] = pack_h(e23.x * md1[jj].x, e23.y * md1[jj].y);
            }
        }
        #pragma unroll
        for (int off = 1; off <= 2; off <<= 1) {
            zs0 += __shfl_xor_sync(0xffffffffu, zs0, off);
            zs1 += __shfl_xor_sync(0xffffffffu, zs1, off);
        }
        z_run0 += zs0; z_run1 += zs1;
        m_run0 = mnew0; m_run1 = mnew1;

        #pragma unroll
        for (int ks = 0; ks < 4; ks++) {
            uint32_t af[4] = { Pr0[2*ks], Pr1[2*ks], Pr0[2*ks+1], Pr1[2*ks+1] };
            uint32_t vf[8][2];
            #pragma unroll
            for (int p = 0; p < 4; p++) {
                uint32_t rr[4];
                ldsm4(rr, vsAddr + (uint32_t)((p * 16 + bRow) * APW
                                              + ks * 8 + bCol) * 4);
                vf[2*p][0]   = rr[0]; vf[2*p][1]   = rr[1];
                vf[2*p+1][0] = rr[2]; vf[2*p+1][1] = rr[3];
            }
            #pragma unroll
            for (int nt = 0; nt < 8; nt++)
                mma16(Of[nt], af, vf[nt]);
        }
    }

    const float inv0 = 1.f / z_run0, inv1 = 1.f / z_run1;
    #pragma unroll
    for (int nt = 0; nt < 8; nt++) {
        const int d = h * DKH + nt * 8 + 2 * t;
        *(uint32_t*)(ctx + ((size_t)b * SEQ + qi0) * DIM + d) =
            pack_h(Of[nt][0] * inv0, Of[nt][1] * inv0);
        *(uint32_t*)(ctx + ((size_t)b * SEQ + qi1) * DIM + d) =
            pack_h(Of[nt][2] * inv1, Of[nt][3] * inv1);
    }
}

// ---------------- host ----------------
extern "C" void kernel_launch(void* const* d_in, const int* in_sizes, int n_in,
                              void* d_out, int out_size)
{
    const float* Q    = (const float*)d_in[0];
    const float* Kin  = (const float*)d_in[1];
    const float* Vin  = (const float*)d_in[2];
    const float* dist = (const float*)d_in[3];
    const float* Wq   = (const float*)d_in[4];
    const float* bq   = (const float*)d_in[5];
    const float* Wk   = (const float*)d_in[6];
    const float* bk   = (const float*)d_in[7];
    const float* Wv   = (const float*)d_in[8];
    const float* bv   = (const float*)d_in[9];
    const float* Wo   = (const float*)d_in[10];
    const float* bo   = (const float*)d_in[11];
    float* out = (float*)d_out;

    __half *qin, *kin, *vin, *qh, *kh, *vtb, *ctxb, *dmh;
    __half *wqh, *wkh, *wvh, *woh, *woT, *wkv;
    float *bkv, *zero;
    cudaGetSymbolAddress((void**)&qin,  g_qin);
    cudaGetSymbolAddress((void**)&kin,  g_kin);
    cudaGetSymbolAddress((void**)&vin,  g_vin);
    cudaGetSymbolAddress((void**)&qh,   g_qh);
    cudaGetSymbolAddress((void**)&kh,   g_kh);
    cudaGetSymbolAddress((void**)&vtb,  g_vt);
    cudaGetSymbolAddress((void**)&ctxb, g_ctx);
    cudaGetSymbolAddress((void**)&dmh,  g_dmh);
    cudaGetSymbolAddress((void**)&wqh,  g_wq);
    cudaGetSymbolAddress((void**)&wkh,  g_wk);
    cudaGetSymbolAddress((void**)&wvh,  g_wv);
    cudaGetSymbolAddress((void**)&woh,  g_wo);
    cudaGetSymbolAddress((void**)&woT,  g_woT);
    cudaGetSymbolAddress((void**)&wkv,  g_wkv);
    cudaGetSymbolAddress((void**)&bkv,  g_bkv);
    cudaGetSymbolAddress((void**)&zero, g_zero);

    cudaFuncSetAttribute(gemm_qkv_kernel,
                         cudaFuncAttributeMaxDynamicSharedMemorySize, GEMM_SMEM);
    cudaFuncSetAttribute(fold_gemm_kernel,
                         cudaFuncAttributeMaxDynamicSharedMemorySize, GEMM_SMEM);
    cudaFuncSetAttribute(gemm_ofin_kernel,
                         cudaFuncAttributeMaxDynamicSharedMemorySize, GEMM_SMEM);
    cudaFuncSetAttribute(attn_h_kernel,
                         cudaFuncAttributeMaxDynamicSharedMemorySize, ATTN_SMEM);

    {
        const int nAct4 = MTOT * DIM / 4;
        const int nW4   = NL * D2 / 4;
        const int nD4   = BSZ * SEQ * SEQ / 4;
        dim3 ga((nAct4 + 255) / 256, 3);
        f2h_acts_kernel<<<ga, 256>>>((const float4*)Q, (const float4*)Kin,
                                     (const float4*)Vin,
                                     (uint2*)qin, (uint2*)kin, (uint2*)vin, nAct4);
        dim3 gw((nW4 + 255) / 256, 4);
        f2h_w_kernel<<<gw, 256>>>((const float4*)Wq, (const float4*)Wk,
                                  (const float4*)Wv, (const float4*)Wo,
                                  (uint2*)wqh, (uint2*)wkh, (uint2*)wvh, (uint2*)woh, nW4);
        f2h_dist_kernel<<<(nD4 + 255) / 256, 256>>>((const float4*)dist,
                                                    (uint2*)dmh, nD4);
        dim3 gt(24, 24, 2);
        transpose_w_kernel<<<gt, dim3(32, 8)>>>(woh, woT);
        dim3 gf(6, 6, 4);
        fold_gemm_kernel<<<gf, 256, GEMM_SMEM>>>(wkh, wvh, woT, zero, wkv);
        dim3 gb(6, 4);
        biasfold_kernel<<<gb, 128>>>(Wk, Wv, bk, bv, bo, bkv);
    }

    const float qscale = 0.125f * 1.4426950408889634f;  // log2(e)/sqrt(64)
    dim3 qkvgrid(18, MTOT / 128);
    dim3 ogrid(DIM / 128, MTOT / 128);
    dim3 agrid(SEQ / 128, NH, BSZ);

    // layer 1
    gemm_qkv_kernel<<<qkvgrid, 256, GEMM_SMEM>>>(
        qin, kin, vin, wqh, wkh, wvh, bq, bk, bv, qh, kh, vtb, qscale);
    attn_h_kernel<<<agrid, 256, ATTN_SMEM>>>(qh, kh, vtb, dmh, ctxb);
    // layer 2 (folded K/V from ctx)
    gemm_qkv_kernel<<<qkvgrid, 256, GEMM_SMEM>>>(
        qin, ctxb, ctxb, wqh + D2, wkv, wkv + D2,
        bq + DIM, bkv, bkv + DIM, qh, kh, vtb, qscale);
    attn_h_kernel<<<agrid, 256, ATTN_SMEM>>>(qh, kh, vtb, dmh, ctxb);
    // layer 3 (folded)
    gemm_qkv_kernel<<<qkvgrid, 256, GEMM_SMEM>>>(
        qin, ctxb, ctxb, wqh + 2 * (size_t)D2, wkv + 2 * (size_t)D2, wkv + 3 * (size_t)D2,
        bq + 2 * DIM, bkv + 2 * DIM, bkv + 3 * DIM, qh, kh, vtb, qscale);
    attn_h_kernel<<<agrid, 256, ATTN_SMEM>>>(qh, kh, vtb, dmh, ctxb);
    // final
    gemm_ofin_kernel<<<ogrid, 256, GEMM_SMEM>>>(ctxb, woh + 2 * (size_t)D2,
                                                bo + 2 * DIM, Vin, out);
}